// round 1
// baseline (speedup 1.0000x reference)
#include <cuda_runtime.h>
#include <cuda_bf16.h>
#include <math_constants.h>

// Problem constants
#define BB   8
#define SEQ  2048
#define DIM  1024
#define MTOT (BB * SEQ)          // 16384 rows of x

// Scratch (allocation-free rule: __device__ globals)
__device__ float g_Q[(size_t)BB * SEQ * DIM];           // 64 MB
__device__ float g_K[(size_t)BB * SEQ * DIM];           // 64 MB
__device__ float g_V[(size_t)BB * SEQ * DIM];           // 64 MB
__device__ float g_S[(size_t)BB * SEQ * SEQ];           // 134 MB (scores -> probs in place)

// ---------------------------------------------------------------------------
// Kernel 1: fused QKV projection.  Y = X[16384,1024] * W[1024,1024]
// blockIdx.z selects {Wq->g_Q, Wk->g_K, Wv->g_V}.
// 128x128 block tile, BK=8, 8x8 per-thread micro-tile, 256 threads.
// ---------------------------------------------------------------------------
__global__ void __launch_bounds__(256) qkv_kernel(
    const float* __restrict__ X,
    const float* __restrict__ Wq,
    const float* __restrict__ Wk,
    const float* __restrict__ Wv)
{
    __shared__ float As[8][128];   // transposed A tile: As[k][m]
    __shared__ float Bs[8][128];   // B tile: Bs[k][n]

    const int t = threadIdx.x;
    const int rowBase = blockIdx.y * 128;
    const int colBase = blockIdx.x * 128;

    const float* W;
    float* Out;
    if (blockIdx.z == 0)      { W = Wq; Out = g_Q; }
    else if (blockIdx.z == 1) { W = Wk; Out = g_K; }
    else                      { W = Wv; Out = g_V; }

    const int aRow = t >> 1;            // 0..127
    const int aCol = (t & 1) * 4;       // 0 or 4
    const int bRow = t >> 5;            // 0..7
    const int bCol = (t & 31) * 4;      // 0..124
    const int tx = t & 15;              // col group
    const int ty = t >> 4;              // row group

    float acc[8][8] = {};

    for (int k0 = 0; k0 < DIM; k0 += 8) {
        float4 av = *(const float4*)&X[(size_t)(rowBase + aRow) * DIM + k0 + aCol];
        As[aCol + 0][aRow] = av.x;
        As[aCol + 1][aRow] = av.y;
        As[aCol + 2][aRow] = av.z;
        As[aCol + 3][aRow] = av.w;
        float4 bv = *(const float4*)&W[(size_t)(k0 + bRow) * DIM + colBase + bCol];
        *(float4*)&Bs[bRow][bCol] = bv;
        __syncthreads();

#pragma unroll
        for (int k = 0; k < 8; k++) {
            float4 a0 = *(const float4*)&As[k][ty * 8];
            float4 a1 = *(const float4*)&As[k][ty * 8 + 4];
            float4 b0 = *(const float4*)&Bs[k][tx * 8];
            float4 b1 = *(const float4*)&Bs[k][tx * 8 + 4];
            float ra[8] = {a0.x, a0.y, a0.z, a0.w, a1.x, a1.y, a1.z, a1.w};
            float rb[8] = {b0.x, b0.y, b0.z, b0.w, b1.x, b1.y, b1.z, b1.w};
#pragma unroll
            for (int i = 0; i < 8; i++)
#pragma unroll
                for (int j = 0; j < 8; j++)
                    acc[i][j] += ra[i] * rb[j];
        }
        __syncthreads();
    }

#pragma unroll
    for (int i = 0; i < 8; i++) {
#pragma unroll
        for (int j = 0; j < 8; j += 4) {
            float4 v = make_float4(acc[i][j], acc[i][j + 1], acc[i][j + 2], acc[i][j + 3]);
            *(float4*)&Out[(size_t)(rowBase + ty * 8 + i) * DIM + colBase + tx * 8 + j] = v;
        }
    }
}

// ---------------------------------------------------------------------------
// Kernel 2: S[b,i,j] = (1/32) * dot(Q[b,i,:], K[b,j,:])  for block pairs jb<=ib
// NT-style GEMM (both operands K-contiguous). Upper-tri blocks early-exit.
// ---------------------------------------------------------------------------
__global__ void __launch_bounds__(256) scores_kernel()
{
    const int jb = blockIdx.x;
    const int ib = blockIdx.y;
    if (jb > ib) return;               // causal: skip upper triangle
    const int b = blockIdx.z;

    __shared__ float Qs[8][128];       // Qs[k][i]
    __shared__ float Ks[8][128];       // Ks[k][j]

    const float* Qb = g_Q + (size_t)b * SEQ * DIM;
    const float* Kb = g_K + (size_t)b * SEQ * DIM;
    float* Sb = g_S + (size_t)b * SEQ * SEQ;

    const int t = threadIdx.x;
    const int aRow = t >> 1;
    const int aCol = (t & 1) * 4;
    const int tx = t & 15;
    const int ty = t >> 4;
    const int iBase = ib * 128;
    const int jBase = jb * 128;

    float acc[8][8] = {};

    for (int k0 = 0; k0 < DIM; k0 += 8) {
        float4 qv = *(const float4*)&Qb[(size_t)(iBase + aRow) * DIM + k0 + aCol];
        Qs[aCol + 0][aRow] = qv.x;
        Qs[aCol + 1][aRow] = qv.y;
        Qs[aCol + 2][aRow] = qv.z;
        Qs[aCol + 3][aRow] = qv.w;
        float4 kv = *(const float4*)&Kb[(size_t)(jBase + aRow) * DIM + k0 + aCol];
        Ks[aCol + 0][aRow] = kv.x;
        Ks[aCol + 1][aRow] = kv.y;
        Ks[aCol + 2][aRow] = kv.z;
        Ks[aCol + 3][aRow] = kv.w;
        __syncthreads();

#pragma unroll
        for (int k = 0; k < 8; k++) {
            float4 a0 = *(const float4*)&Qs[k][ty * 8];
            float4 a1 = *(const float4*)&Qs[k][ty * 8 + 4];
            float4 b0 = *(const float4*)&Ks[k][tx * 8];
            float4 b1 = *(const float4*)&Ks[k][tx * 8 + 4];
            float ra[8] = {a0.x, a0.y, a0.z, a0.w, a1.x, a1.y, a1.z, a1.w};
            float rb[8] = {b0.x, b0.y, b0.z, b0.w, b1.x, b1.y, b1.z, b1.w};
#pragma unroll
            for (int i = 0; i < 8; i++)
#pragma unroll
                for (int j = 0; j < 8; j++)
                    acc[i][j] += ra[i] * rb[j];
        }
        __syncthreads();
    }

    const float scale = 0.03125f;  // 1/sqrt(1024)
#pragma unroll
    for (int i = 0; i < 8; i++) {
#pragma unroll
        for (int j = 0; j < 8; j += 4) {
            float4 v = make_float4(acc[i][j] * scale, acc[i][j + 1] * scale,
                                   acc[i][j + 2] * scale, acc[i][j + 3] * scale);
            *(float4*)&Sb[(size_t)(iBase + ty * 8 + i) * SEQ + jBase + tx * 8 + j] = v;
        }
    }
}

// ---------------------------------------------------------------------------
// Kernel 3: causal softmax over S row prefix [0..i]; writes probs in place,
// zero-pads (i, blockBoundary) so the PV GEMM can consume full diagonal tiles.
// One block per (b,i) row; each thread holds up to 8 values in registers.
// ---------------------------------------------------------------------------
__global__ void __launch_bounds__(256) softmax_kernel()
{
    const int row = blockIdx.x;            // 0..16383
    const int b = row >> 11;
    const int i = row & (SEQ - 1);
    float* Srow = g_S + (size_t)b * SEQ * SEQ + (size_t)i * SEQ;
    const int L = i + 1;
    const int Lpad = ((i >> 7) + 1) << 7;  // diagonal 128-block boundary
    const int t = threadIdx.x;

    float vals[8];
    float mx = -CUDART_INF_F;
#pragma unroll
    for (int r = 0; r < 8; r++) {
        const int j = t + r * 256;
        vals[r] = (j < L) ? Srow[j] : -CUDART_INF_F;
        mx = fmaxf(mx, vals[r]);
    }

    __shared__ float red[256];
    red[t] = mx;
    __syncthreads();
    for (int s = 128; s > 0; s >>= 1) {
        if (t < s) red[t] = fmaxf(red[t], red[t + s]);
        __syncthreads();
    }
    mx = red[0];
    __syncthreads();

    float sum = 0.f;
#pragma unroll
    for (int r = 0; r < 8; r++) {
        const int j = t + r * 256;
        vals[r] = (j < L) ? __expf(vals[r] - mx) : 0.f;
        sum += vals[r];
    }
    red[t] = sum;
    __syncthreads();
    for (int s = 128; s > 0; s >>= 1) {
        if (t < s) red[t] += red[t + s];
        __syncthreads();
    }
    const float inv = 1.f / red[0];

#pragma unroll
    for (int r = 0; r < 8; r++) {
        const int j = t + r * 256;
        if (j < Lpad) Srow[j] = vals[r] * inv;   // zeros for L <= j < Lpad
    }
}

// ---------------------------------------------------------------------------
// Kernel 4: O[b,i,:] = sum_{m<=i} P[b,i,m] * V[b,m,:]
// NN GEMM per batch; k-loop bounded at the diagonal block (causality).
// ---------------------------------------------------------------------------
__global__ void __launch_bounds__(256) pv_kernel(float* __restrict__ Out)
{
    const int db = blockIdx.x;   // 0..7  (DIM/128)
    const int ib = blockIdx.y;   // 0..15 (SEQ/128)
    const int b = blockIdx.z;

    __shared__ float As[8][128];  // As[k][i]  (P tile, transposed)
    __shared__ float Bs[8][128];  // Bs[k][d]  (V tile)

    const float* P = g_S + (size_t)b * SEQ * SEQ;
    const float* Vb = g_V + (size_t)b * SEQ * DIM;
    float* Ob = Out + (size_t)b * SEQ * DIM;

    const int t = threadIdx.x;
    const int aRow = t >> 1;
    const int aCol = (t & 1) * 4;
    const int bRow = t >> 5;
    const int bCol = (t & 31) * 4;
    const int tx = t & 15;
    const int ty = t >> 4;
    const int iBase = ib * 128;
    const int dBase = db * 128;
    const int kEnd = (ib + 1) * 128;     // causal bound

    float acc[8][8] = {};

    for (int k0 = 0; k0 < kEnd; k0 += 8) {
        float4 av = *(const float4*)&P[(size_t)(iBase + aRow) * SEQ + k0 + aCol];
        As[aCol + 0][aRow] = av.x;
        As[aCol + 1][aRow] = av.y;
        As[aCol + 2][aRow] = av.z;
        As[aCol + 3][aRow] = av.w;
        float4 bv = *(const float4*)&Vb[(size_t)(k0 + bRow) * DIM + dBase + bCol];
        *(float4*)&Bs[bRow][bCol] = bv;
        __syncthreads();

#pragma unroll
        for (int k = 0; k < 8; k++) {
            float4 a0 = *(const float4*)&As[k][ty * 8];
            float4 a1 = *(const float4*)&As[k][ty * 8 + 4];
            float4 b0 = *(const float4*)&Bs[k][tx * 8];
            float4 b1 = *(const float4*)&Bs[k][tx * 8 + 4];
            float ra[8] = {a0.x, a0.y, a0.z, a0.w, a1.x, a1.y, a1.z, a1.w};
            float rb[8] = {b0.x, b0.y, b0.z, b0.w, b1.x, b1.y, b1.z, b1.w};
#pragma unroll
            for (int i = 0; i < 8; i++)
#pragma unroll
                for (int j = 0; j < 8; j++)
                    acc[i][j] += ra[i] * rb[j];
        }
        __syncthreads();
    }

#pragma unroll
    for (int i = 0; i < 8; i++) {
#pragma unroll
        for (int j = 0; j < 8; j += 4) {
            float4 v = make_float4(acc[i][j], acc[i][j + 1], acc[i][j + 2], acc[i][j + 3]);
            *(float4*)&Ob[(size_t)(iBase + ty * 8 + i) * DIM + dBase + tx * 8 + j] = v;
        }
    }
}

// ---------------------------------------------------------------------------
extern "C" void kernel_launch(void* const* d_in, const int* in_sizes, int n_in,
                              void* d_out, int out_size)
{
    const float* x  = (const float*)d_in[0];
    const float* Wq = (const float*)d_in[1];
    const float* Wk = (const float*)d_in[2];
    const float* Wv = (const float*)d_in[3];
    float* out = (float*)d_out;

    qkv_kernel<<<dim3(DIM / 128, MTOT / 128, 3), 256>>>(x, Wq, Wk, Wv);
    scores_kernel<<<dim3(SEQ / 128, SEQ / 128, BB), 256>>>();
    softmax_kernel<<<MTOT, 256>>>();
    pv_kernel<<<dim3(DIM / 128, SEQ / 128, BB), 256>>>(out);
}

// round 3
// speedup vs baseline: 3.5353x; 3.5353x over previous
#include <cuda_runtime.h>
#include <cuda_bf16.h>
#include <math_constants.h>
#include <cstdint>

// ---------------------------------------------------------------------------
// CausalAttention B=8, N=2048, d=1024, fp32 — legacy tensor-core path.
// mma.sync.m16n8k8 tf32 (compiles under compute_103; tcgen05 does NOT).
// All GEMMs NT-form (both operands K-contiguous): W and V pre-transposed.
// ---------------------------------------------------------------------------

#define BB   8
#define SEQ  2048
#define DIM  1024
#define MTOT (BB * SEQ)

// Scratch (__device__ globals per allocation-free rule)
__device__ float g_Xr[(size_t)MTOT * DIM];
__device__ float g_Wt[3][(size_t)DIM * DIM];
__device__ float g_Q [(size_t)MTOT * DIM];
__device__ float g_K [(size_t)MTOT * DIM];
__device__ float g_V [(size_t)MTOT * DIM];
__device__ float g_Vt[(size_t)BB * DIM * SEQ];
__device__ float g_S [(size_t)BB * SEQ * SEQ];

__device__ __forceinline__ uint32_t smem_u32(const void* p) {
    uint32_t a;
    asm("{ .reg .u64 t; cvta.to.shared.u64 t, %1; cvt.u32.u64 %0, t; }"
        : "=r"(a) : "l"(p));
    return a;
}
__device__ __forceinline__ float rtf32(float x) {
    uint32_t r;
    asm("cvt.rna.tf32.f32 %0, %1;" : "=r"(r) : "f"(x));
    return __uint_as_float(r);
}

#define CP_ASYNC16(dst, src) \
    asm volatile("cp.async.cg.shared.global [%0], [%1], 16;" :: "r"(dst), "l"(src) : "memory")
#define CP_COMMIT()  asm volatile("cp.async.commit_group;" ::: "memory")
#define CP_WAIT(n)   asm volatile("cp.async.wait_group %0;" :: "n"(n) : "memory")

__device__ __forceinline__ void mma_tf32(float& c0, float& c1, float& c2, float& c3,
                                         uint32_t a0, uint32_t a1, uint32_t a2, uint32_t a3,
                                         uint32_t b0, uint32_t b1) {
    asm volatile(
        "mma.sync.aligned.m16n8k8.row.col.f32.tf32.tf32.f32 "
        "{%0,%1,%2,%3}, {%4,%5,%6,%7}, {%8,%9}, {%0,%1,%2,%3};"
        : "+f"(c0), "+f"(c1), "+f"(c2), "+f"(c3)
        : "r"(a0), "r"(a1), "r"(a2), "r"(a3), "r"(b0), "r"(b1));
}

// ---------------------------------------------------------------------------
// 128x128 x K tile GEMM core. C[i][j] = scale * sum_k A[i][k]*B[j][k].
// 256 threads = 8 warps (2 x 4), warp tile 64x32. BK=32, double-buffered.
// Smem stride 36 floats (pad 4) -> conflict-free fragment loads.
// ---------------------------------------------------------------------------
#define BK 32
#define KST 36                  // padded row stride (floats)
#define TILE_F (128 * KST)      // floats per operand per stage
#define SMEM_DYN (4 * TILE_F * 4)   // 2 ops * 2 stages * 18432B = 73728B

__device__ __forceinline__ void load_tile(uint32_t smBase,
                                          const float* __restrict__ G,
                                          int ld, int k0, int t) {
#pragma unroll
    for (int i = 0; i < 4; i++) {
        int idx = t + i * 256;          // 0..1023
        int row = idx >> 3, seg = idx & 7;
        uint32_t d = smBase + (uint32_t)(row * KST + seg * 4) * 4u;
        CP_ASYNC16(d, G + (size_t)row * ld + k0 + seg * 4);
    }
}

__device__ __forceinline__ void gemm_core(const float* __restrict__ A,
                                          const float* __restrict__ B,
                                          float* __restrict__ C,
                                          int lda, int ldb, int ldc,
                                          int nChunks, float scale, int doRound) {
    extern __shared__ float dsm[];
    const uint32_t smA = smem_u32(dsm);                    // A: 2 stages
    const uint32_t smB = smA + 2u * TILE_F * 4u;           // B: 2 stages

    const int t = threadIdx.x;
    const int wid = t >> 5, lane = t & 31;
    const int gid = lane >> 2, t4 = lane & 3;
    const int warpM = wid >> 2;            // 0..1
    const int warpN = wid & 3;             // 0..3
    const int baseM = warpM * 64;
    const int baseN = warpN * 32;

    float acc[4][4][4] = {};

    // prologue: stage 0 <- chunk 0
    load_tile(smA, A, lda, 0, t);
    load_tile(smB, B, ldb, 0, t);
    CP_COMMIT();

    for (int c = 0; c < nChunks; c++) {
        const int s = c & 1;
        if (c + 1 < nChunks) {
            const uint32_t so = (uint32_t)((s ^ 1) * TILE_F) * 4u;
            load_tile(smA + so, A, lda, (c + 1) * BK, t);
            load_tile(smB + so, B, ldb, (c + 1) * BK, t);
            CP_COMMIT();
            CP_WAIT(1);
        } else {
            CP_WAIT(0);
        }
        __syncthreads();

        const uint32_t* As = (const uint32_t*)dsm + (size_t)s * TILE_F;
        const uint32_t* Bs = (const uint32_t*)dsm + 2 * TILE_F + (size_t)s * TILE_F;

#pragma unroll
        for (int kk = 0; kk < BK; kk += 8) {
            uint32_t af[4][4], bf[4][2];
#pragma unroll
            for (int mt = 0; mt < 4; mt++) {
                const uint32_t* p = As + (size_t)(baseM + mt * 16 + gid) * KST + kk + t4;
                af[mt][0] = p[0];
                af[mt][1] = p[8 * KST];
                af[mt][2] = p[4];
                af[mt][3] = p[8 * KST + 4];
            }
#pragma unroll
            for (int nt = 0; nt < 4; nt++) {
                const uint32_t* q = Bs + (size_t)(baseN + nt * 8 + gid) * KST + kk + t4;
                bf[nt][0] = q[0];
                bf[nt][1] = q[4];
            }
#pragma unroll
            for (int mt = 0; mt < 4; mt++)
#pragma unroll
                for (int nt = 0; nt < 4; nt++)
                    mma_tf32(acc[mt][nt][0], acc[mt][nt][1], acc[mt][nt][2], acc[mt][nt][3],
                             af[mt][0], af[mt][1], af[mt][2], af[mt][3],
                             bf[nt][0], bf[nt][1]);
        }
        __syncthreads();
    }

    // epilogue
#pragma unroll
    for (int mt = 0; mt < 4; mt++) {
        const int r0 = baseM + mt * 16 + gid;
#pragma unroll
        for (int nt = 0; nt < 4; nt++) {
            const int col = baseN + nt * 8 + t4 * 2;
            float2 v0, v1;
            v0.x = acc[mt][nt][0] * scale; v0.y = acc[mt][nt][1] * scale;
            v1.x = acc[mt][nt][2] * scale; v1.y = acc[mt][nt][3] * scale;
            if (doRound) {
                v0.x = rtf32(v0.x); v0.y = rtf32(v0.y);
                v1.x = rtf32(v1.x); v1.y = rtf32(v1.y);
            }
            *(float2*)(C + (size_t)r0 * ldc + col) = v0;
            *(float2*)(C + (size_t)(r0 + 8) * ldc + col) = v1;
        }
    }
}

// ---------------------------------------------------------------------------
// Prep / transpose kernels
// ---------------------------------------------------------------------------
__global__ void __launch_bounds__(256) prep_x(const float* __restrict__ x) {
    size_t i = (size_t)blockIdx.x * 256 + threadIdx.x;
    float4 v = ((const float4*)x)[i];
    v.x = rtf32(v.x); v.y = rtf32(v.y); v.z = rtf32(v.z); v.w = rtf32(v.w);
    ((float4*)g_Xr)[i] = v;
}

__global__ void __launch_bounds__(256) transpose_w(const float* __restrict__ Wq,
                                                   const float* __restrict__ Wk,
                                                   const float* __restrict__ Wv) {
    __shared__ float tile[32][33];
    const int z = blockIdx.z;
    const float* W = (z == 0) ? Wq : (z == 1) ? Wk : Wv;
    float* Wt = g_Wt[z];
    const int nBase = blockIdx.x * 32, kBase = blockIdx.y * 32;
    const int tx = threadIdx.x & 31, ty = threadIdx.x >> 5;
#pragma unroll
    for (int r = 0; r < 32; r += 8)
        tile[ty + r][tx] = rtf32(W[(size_t)(kBase + ty + r) * DIM + nBase + tx]);
    __syncthreads();
#pragma unroll
    for (int r = 0; r < 32; r += 8)
        Wt[(size_t)(nBase + ty + r) * DIM + kBase + tx] = tile[tx][ty + r];
}

__global__ void __launch_bounds__(256) transpose_v() {
    __shared__ float tile[32][33];
    const int b = blockIdx.z;
    const int mBase = blockIdx.x * 32, dBase = blockIdx.y * 32;
    const float* V = g_V + (size_t)b * SEQ * DIM;
    float* Vt = g_Vt + (size_t)b * DIM * SEQ;
    const int tx = threadIdx.x & 31, ty = threadIdx.x >> 5;
#pragma unroll
    for (int r = 0; r < 32; r += 8)
        tile[ty + r][tx] = V[(size_t)(mBase + ty + r) * DIM + dBase + tx];
    __syncthreads();
#pragma unroll
    for (int r = 0; r < 32; r += 8)
        Vt[(size_t)(dBase + ty + r) * SEQ + mBase + tx] = tile[tx][ty + r];
}

// ---------------------------------------------------------------------------
// GEMM wrappers
// ---------------------------------------------------------------------------
__global__ void __launch_bounds__(256) qkv_gemm() {
    const int nb = blockIdx.x, mb = blockIdx.y, z = blockIdx.z;
    const float* A = g_Xr + (size_t)mb * 128 * DIM;
    const float* B = g_Wt[z] + (size_t)nb * 128 * DIM;
    float* outp = (z == 0) ? g_Q : (z == 1) ? g_K : g_V;
    float* C = outp + (size_t)mb * 128 * DIM + nb * 128;
    gemm_core(A, B, C, DIM, DIM, DIM, DIM / BK, 1.0f, 1);
}

__global__ void __launch_bounds__(256) scores_gemm() {
    const int jb = blockIdx.x, ib = blockIdx.y, b = blockIdx.z;
    if (jb > ib) return;                       // causal pruning
    const float* A = g_Q + ((size_t)b * SEQ + ib * 128) * DIM;
    const float* B = g_K + ((size_t)b * SEQ + jb * 128) * DIM;
    float* C = g_S + (size_t)b * SEQ * SEQ + (size_t)ib * 128 * SEQ + jb * 128;
    gemm_core(A, B, C, DIM, DIM, SEQ, DIM / BK, 0.03125f, 0);
}

__global__ void __launch_bounds__(256) pv_gemm(float* __restrict__ Out) {
    const int db = blockIdx.x, ib = blockIdx.y, b = blockIdx.z;
    const float* A = g_S + (size_t)b * SEQ * SEQ + (size_t)ib * 128 * SEQ;
    const float* B = g_Vt + ((size_t)b * DIM + db * 128) * SEQ;
    float* C = Out + ((size_t)b * SEQ + ib * 128) * DIM + db * 128;
    gemm_core(A, B, C, SEQ, SEQ, DIM, (ib + 1) * 128 / BK, 1.0f, 0);
}

// ---------------------------------------------------------------------------
// Causal softmax; rounds P to tf32, zero-pads to diagonal block boundary.
// ---------------------------------------------------------------------------
__global__ void __launch_bounds__(256) softmax_kernel() {
    const int row = blockIdx.x;
    const int b = row >> 11;
    const int i = row & (SEQ - 1);
    float* Srow = g_S + (size_t)b * SEQ * SEQ + (size_t)i * SEQ;
    const int L = i + 1;
    const int Lpad = ((i >> 7) + 1) << 7;
    const int t = threadIdx.x;

    float vals[8];
    float mx = -CUDART_INF_F;
#pragma unroll
    for (int r = 0; r < 8; r++) {
        const int j = t + r * 256;
        vals[r] = (j < L) ? Srow[j] : -CUDART_INF_F;
        mx = fmaxf(mx, vals[r]);
    }
    __shared__ float red[256];
    red[t] = mx;
    __syncthreads();
    for (int s = 128; s > 0; s >>= 1) {
        if (t < s) red[t] = fmaxf(red[t], red[t + s]);
        __syncthreads();
    }
    mx = red[0];
    __syncthreads();

    float sum = 0.f;
#pragma unroll
    for (int r = 0; r < 8; r++) {
        const int j = t + r * 256;
        vals[r] = (j < L) ? __expf(vals[r] - mx) : 0.f;
        sum += vals[r];
    }
    red[t] = sum;
    __syncthreads();
    for (int s = 128; s > 0; s >>= 1) {
        if (t < s) red[t] += red[t + s];
        __syncthreads();
    }
    const float inv = 1.f / red[0];
#pragma unroll
    for (int r = 0; r < 8; r++) {
        const int j = t + r * 256;
        if (j < Lpad) Srow[j] = rtf32(vals[r] * inv);
    }
}

// ---------------------------------------------------------------------------
extern "C" void kernel_launch(void* const* d_in, const int* in_sizes, int n_in,
                              void* d_out, int out_size) {
    const float* x  = (const float*)d_in[0];
    const float* Wq = (const float*)d_in[1];
    const float* Wk = (const float*)d_in[2];
    const float* Wv = (const float*)d_in[3];
    float* out = (float*)d_out;

    static int attrDone = 0;
    if (!attrDone) {
        cudaFuncSetAttribute(qkv_gemm,    cudaFuncAttributeMaxDynamicSharedMemorySize, SMEM_DYN);
        cudaFuncSetAttribute(scores_gemm, cudaFuncAttributeMaxDynamicSharedMemorySize, SMEM_DYN);
        cudaFuncSetAttribute(pv_gemm,     cudaFuncAttributeMaxDynamicSharedMemorySize, SMEM_DYN);
        attrDone = 1;
    }

    prep_x<<<(MTOT * DIM / 4) / 256, 256>>>(x);
    transpose_w<<<dim3(32, 32, 3), 256>>>(Wq, Wk, Wv);
    qkv_gemm<<<dim3(DIM / 128, MTOT / 128, 3), 256, SMEM_DYN>>>();
    transpose_v<<<dim3(SEQ / 32, DIM / 32, BB), 256>>>();
    scores_gemm<<<dim3(SEQ / 128, SEQ / 128, BB), 256, SMEM_DYN>>>();
    softmax_kernel<<<MTOT, 256>>>();
    pv_gemm<<<dim3(DIM / 128, SEQ / 128, BB), 256, SMEM_DYN>>>(out);
}

// round 4
// speedup vs baseline: 3.7182x; 1.0518x over previous
#include <cuda_runtime.h>
#include <cuda_bf16.h>
#include <math_constants.h>
#include <cstdint>

// ---------------------------------------------------------------------------
// CausalAttention B=8, N=2048, d=1024, fp32 — legacy tensor-core path.
// mma.sync.m16n8k8 tf32. R4: 64x64 warp tiles (4 warps/CTA) to halve
// smem-crossbar fragment traffic (was the R3 bottleneck).
// ---------------------------------------------------------------------------

#define BB   8
#define SEQ  2048
#define DIM  1024
#define MTOT (BB * SEQ)

__device__ float g_Xr[(size_t)MTOT * DIM];
__device__ float g_Wt[3][(size_t)DIM * DIM];
__device__ float g_Q [(size_t)MTOT * DIM];
__device__ float g_K [(size_t)MTOT * DIM];
__device__ float g_V [(size_t)MTOT * DIM];
__device__ float g_Vt[(size_t)BB * DIM * SEQ];
__device__ float g_S [(size_t)BB * SEQ * SEQ];

__device__ __forceinline__ uint32_t smem_u32(const void* p) {
    uint32_t a;
    asm("{ .reg .u64 t; cvta.to.shared.u64 t, %1; cvt.u32.u64 %0, t; }"
        : "=r"(a) : "l"(p));
    return a;
}
__device__ __forceinline__ float rtf32(float x) {
    uint32_t r;
    asm("cvt.rna.tf32.f32 %0, %1;" : "=r"(r) : "f"(x));
    return __uint_as_float(r);
}

#define CP_ASYNC16(dst, src) \
    asm volatile("cp.async.cg.shared.global [%0], [%1], 16;" :: "r"(dst), "l"(src) : "memory")
#define CP_COMMIT()  asm volatile("cp.async.commit_group;" ::: "memory")
#define CP_WAIT(n)   asm volatile("cp.async.wait_group %0;" :: "n"(n) : "memory")

__device__ __forceinline__ void mma_tf32(float& c0, float& c1, float& c2, float& c3,
                                         uint32_t a0, uint32_t a1, uint32_t a2, uint32_t a3,
                                         uint32_t b0, uint32_t b1) {
    asm volatile(
        "mma.sync.aligned.m16n8k8.row.col.f32.tf32.tf32.f32 "
        "{%0,%1,%2,%3}, {%4,%5,%6,%7}, {%8,%9}, {%0,%1,%2,%3};"
        : "+f"(c0), "+f"(c1), "+f"(c2), "+f"(c3)
        : "r"(a0), "r"(a1), "r"(a2), "r"(a3), "r"(b0), "r"(b1));
}

// ---------------------------------------------------------------------------
// 128x128 x K tile GEMM core. 128 threads = 4 warps (2x2), warp tile 64x64.
// BK=32 double-buffered cp.async. Smem stride 36 floats (conflict-free).
// ---------------------------------------------------------------------------
#define BK 32
#define KST 36
#define TILE_F (128 * KST)
#define SMEM_DYN (4 * TILE_F * 4)   // 73728 B -> 2 CTAs/SM

__device__ __forceinline__ void load_tile(uint32_t smBase,
                                          const float* __restrict__ G,
                                          int ld, int k0, int t) {
#pragma unroll
    for (int i = 0; i < 8; i++) {
        int idx = t + i * 128;          // 0..1023
        int row = idx >> 3, seg = idx & 7;
        uint32_t d = smBase + (uint32_t)(row * KST + seg * 4) * 4u;
        CP_ASYNC16(d, G + (size_t)row * ld + k0 + seg * 4);
    }
}

__device__ __forceinline__ void gemm_core(const float* __restrict__ A,
                                          const float* __restrict__ B,
                                          float* __restrict__ C,
                                          int lda, int ldb, int ldc,
                                          int nChunks, float scale, int doRound) {
    extern __shared__ float dsm[];
    const uint32_t smA = smem_u32(dsm);
    const uint32_t smB = smA + 2u * TILE_F * 4u;

    const int t = threadIdx.x;
    const int wid = t >> 5, lane = t & 31;
    const int gid = lane >> 2, t4 = lane & 3;
    const int baseM = (wid >> 1) * 64;      // warpM 0..1
    const int baseN = (wid & 1) * 64;       // warpN 0..1

    float acc[4][8][4] = {};

    load_tile(smA, A, lda, 0, t);
    load_tile(smB, B, ldb, 0, t);
    CP_COMMIT();

    for (int c = 0; c < nChunks; c++) {
        const int s = c & 1;
        if (c + 1 < nChunks) {
            const uint32_t so = (uint32_t)((s ^ 1) * TILE_F) * 4u;
            load_tile(smA + so, A, lda, (c + 1) * BK, t);
            load_tile(smB + so, B, ldb, (c + 1) * BK, t);
            CP_COMMIT();
            CP_WAIT(1);
        } else {
            CP_WAIT(0);
        }
        __syncthreads();

        const uint32_t* As = (const uint32_t*)dsm + (size_t)s * TILE_F;
        const uint32_t* Bs = (const uint32_t*)dsm + 2 * TILE_F + (size_t)s * TILE_F;

#pragma unroll
        for (int kk = 0; kk < BK; kk += 8) {
            uint32_t af[4][4], bf[8][2];
#pragma unroll
            for (int mt = 0; mt < 4; mt++) {
                const uint32_t* p = As + (size_t)(baseM + mt * 16 + gid) * KST + kk + t4;
                af[mt][0] = p[0];
                af[mt][1] = p[8 * KST];
                af[mt][2] = p[4];
                af[mt][3] = p[8 * KST + 4];
            }
#pragma unroll
            for (int nt = 0; nt < 8; nt++) {
                const uint32_t* q = Bs + (size_t)(baseN + nt * 8 + gid) * KST + kk + t4;
                bf[nt][0] = q[0];
                bf[nt][1] = q[4];
            }
#pragma unroll
            for (int mt = 0; mt < 4; mt++)
#pragma unroll
                for (int nt = 0; nt < 8; nt++)
                    mma_tf32(acc[mt][nt][0], acc[mt][nt][1], acc[mt][nt][2], acc[mt][nt][3],
                             af[mt][0], af[mt][1], af[mt][2], af[mt][3],
                             bf[nt][0], bf[nt][1]);
        }
        __syncthreads();
    }

#pragma unroll
    for (int mt = 0; mt < 4; mt++) {
        const int r0 = baseM + mt * 16 + gid;
#pragma unroll
        for (int nt = 0; nt < 8; nt++) {
            const int col = baseN + nt * 8 + t4 * 2;
            float2 v0, v1;
            v0.x = acc[mt][nt][0] * scale; v0.y = acc[mt][nt][1] * scale;
            v1.x = acc[mt][nt][2] * scale; v1.y = acc[mt][nt][3] * scale;
            if (doRound) {
                v0.x = rtf32(v0.x); v0.y = rtf32(v0.y);
                v1.x = rtf32(v1.x); v1.y = rtf32(v1.y);
            }
            *(float2*)(C + (size_t)r0 * ldc + col) = v0;
            *(float2*)(C + (size_t)(r0 + 8) * ldc + col) = v1;
        }
    }
}

// ---------------------------------------------------------------------------
// Prep / transpose kernels
// ---------------------------------------------------------------------------
__global__ void __launch_bounds__(256) prep_x(const float* __restrict__ x) {
    size_t i = (size_t)blockIdx.x * 256 + threadIdx.x;
    float4 v = ((const float4*)x)[i];
    v.x = rtf32(v.x); v.y = rtf32(v.y); v.z = rtf32(v.z); v.w = rtf32(v.w);
    ((float4*)g_Xr)[i] = v;
}

__global__ void __launch_bounds__(256) transpose_w(const float* __restrict__ Wq,
                                                   const float* __restrict__ Wk,
                                                   const float* __restrict__ Wv) {
    __shared__ float tile[32][33];
    const int z = blockIdx.z;
    const float* W = (z == 0) ? Wq : (z == 1) ? Wk : Wv;
    float* Wt = g_Wt[z];
    const int nBase = blockIdx.x * 32, kBase = blockIdx.y * 32;
    const int tx = threadIdx.x & 31, ty = threadIdx.x >> 5;
#pragma unroll
    for (int r = 0; r < 32; r += 8)
        tile[ty + r][tx] = rtf32(W[(size_t)(kBase + ty + r) * DIM + nBase + tx]);
    __syncthreads();
#pragma unroll
    for (int r = 0; r < 32; r += 8)
        Wt[(size_t)(nBase + ty + r) * DIM + kBase + tx] = tile[tx][ty + r];
}

__global__ void __launch_bounds__(256) transpose_v() {
    __shared__ float tile[32][33];
    const int b = blockIdx.z;
    const int mBase = blockIdx.x * 32, dBase = blockIdx.y * 32;
    const float* V = g_V + (size_t)b * SEQ * DIM;
    float* Vt = g_Vt + (size_t)b * DIM * SEQ;
    const int tx = threadIdx.x & 31, ty = threadIdx.x >> 5;
#pragma unroll
    for (int r = 0; r < 32; r += 8)
        tile[ty + r][tx] = V[(size_t)(mBase + ty + r) * DIM + dBase + tx];
    __syncthreads();
#pragma unroll
    for (int r = 0; r < 32; r += 8)
        Vt[(size_t)(dBase + ty + r) * SEQ + mBase + tx] = tile[tx][ty + r];
}

// ---------------------------------------------------------------------------
// GEMM wrappers (128 threads, 2 CTAs/SM)
// ---------------------------------------------------------------------------
__global__ void __launch_bounds__(128, 2) qkv_gemm() {
    const int nb = blockIdx.x, mb = blockIdx.y, z = blockIdx.z;
    const float* A = g_Xr + (size_t)mb * 128 * DIM;
    const float* B = g_Wt[z] + (size_t)nb * 128 * DIM;
    float* outp = (z == 0) ? g_Q : (z == 1) ? g_K : g_V;
    float* C = outp + (size_t)mb * 128 * DIM + nb * 128;
    gemm_core(A, B, C, DIM, DIM, DIM, DIM / BK, 1.0f, 1);
}

__global__ void __launch_bounds__(128, 2) scores_gemm() {
    const int jb = blockIdx.x, ib = blockIdx.y, b = blockIdx.z;
    if (jb > ib) return;
    const float* A = g_Q + ((size_t)b * SEQ + ib * 128) * DIM;
    const float* B = g_K + ((size_t)b * SEQ + jb * 128) * DIM;
    float* C = g_S + (size_t)b * SEQ * SEQ + (size_t)ib * 128 * SEQ + jb * 128;
    gemm_core(A, B, C, DIM, DIM, SEQ, DIM / BK, 0.03125f, 0);
}

__global__ void __launch_bounds__(128, 2) pv_gemm(float* __restrict__ Out) {
    const int db = blockIdx.x, ib = blockIdx.y, b = blockIdx.z;
    const float* A = g_S + (size_t)b * SEQ * SEQ + (size_t)ib * 128 * SEQ;
    const float* B = g_Vt + ((size_t)b * DIM + db * 128) * SEQ;
    float* C = Out + ((size_t)b * SEQ + ib * 128) * DIM + db * 128;
    gemm_core(A, B, C, SEQ, SEQ, DIM, (ib + 1) * 128 / BK, 1.0f, 0);
}

// ---------------------------------------------------------------------------
// Causal softmax; rounds P to tf32, zero-pads to diagonal block boundary.
// ---------------------------------------------------------------------------
__global__ void __launch_bounds__(256) softmax_kernel() {
    const int row = blockIdx.x;
    const int b = row >> 11;
    const int i = row & (SEQ - 1);
    float* Srow = g_S + (size_t)b * SEQ * SEQ + (size_t)i * SEQ;
    const int L = i + 1;
    const int Lpad = ((i >> 7) + 1) << 7;
    const int t = threadIdx.x;

    float vals[8];
    float mx = -CUDART_INF_F;
#pragma unroll
    for (int r = 0; r < 8; r++) {
        const int j = t + r * 256;
        vals[r] = (j < L) ? Srow[j] : -CUDART_INF_F;
        mx = fmaxf(mx, vals[r]);
    }
    __shared__ float red[256];
    red[t] = mx;
    __syncthreads();
    for (int s = 128; s > 0; s >>= 1) {
        if (t < s) red[t] = fmaxf(red[t], red[t + s]);
        __syncthreads();
    }
    mx = red[0];
    __syncthreads();

    float sum = 0.f;
#pragma unroll
    for (int r = 0; r < 8; r++) {
        const int j = t + r * 256;
        vals[r] = (j < L) ? __expf(vals[r] - mx) : 0.f;
        sum += vals[r];
    }
    red[t] = sum;
    __syncthreads();
    for (int s = 128; s > 0; s >>= 1) {
        if (t < s) red[t] += red[t + s];
        __syncthreads();
    }
    const float inv = 1.f / red[0];
#pragma unroll
    for (int r = 0; r < 8; r++) {
        const int j = t + r * 256;
        if (j < Lpad) Srow[j] = rtf32(vals[r] * inv);
    }
}

// ---------------------------------------------------------------------------
extern "C" void kernel_launch(void* const* d_in, const int* in_sizes, int n_in,
                              void* d_out, int out_size) {
    const float* x  = (const float*)d_in[0];
    const float* Wq = (const float*)d_in[1];
    const float* Wk = (const float*)d_in[2];
    const float* Wv = (const float*)d_in[3];
    float* out = (float*)d_out;

    static int attrDone = 0;
    if (!attrDone) {
        cudaFuncSetAttribute(qkv_gemm,    cudaFuncAttributeMaxDynamicSharedMemorySize, SMEM_DYN);
        cudaFuncSetAttribute(scores_gemm, cudaFuncAttributeMaxDynamicSharedMemorySize, SMEM_DYN);
        cudaFuncSetAttribute(pv_gemm,     cudaFuncAttributeMaxDynamicSharedMemorySize, SMEM_DYN);
        attrDone = 1;
    }

    prep_x<<<(MTOT * DIM / 4) / 256, 256>>>(x);
    transpose_w<<<dim3(32, 32, 3), 256>>>(Wq, Wk, Wv);
    qkv_gemm<<<dim3(DIM / 128, MTOT / 128, 3), 128, SMEM_DYN>>>();
    transpose_v<<<dim3(SEQ / 32, DIM / 32, BB), 256>>>();
    scores_gemm<<<dim3(SEQ / 128, SEQ / 128, BB), 128, SMEM_DYN>>>();
    softmax_kernel<<<MTOT, 256>>>();
    pv_gemm<<<dim3(DIM / 128, SEQ / 128, BB), 128, SMEM_DYN>>>(out);
}

// round 6
// speedup vs baseline: 4.4532x; 1.1977x over previous
#include <cuda_runtime.h>
#include <cuda_fp16.h>
#include <math_constants.h>
#include <cstdint>

// ---------------------------------------------------------------------------
// CausalAttention B=8, N=2048, d=1024, fp32 I/O — fp16 tensor-core path.
// mma.sync.m16n8k16.f32.f16.f16.f32 (fp16 mantissa == tf32 mantissa, so
// precision matches the R3/R4 tf32 path at 2x the legacy-HMMA rate and
// half the operand bytes everywhere).
// ---------------------------------------------------------------------------

#define BB   8
#define SEQ  2048
#define DIM  1024
#define MTOT (BB * SEQ)

// Scratch (__device__ globals per allocation-free rule) — all half now.
__device__ __half g_Xr[(size_t)MTOT * DIM];
__device__ __half g_Wt[3][(size_t)DIM * DIM];
__device__ __half g_Q [(size_t)MTOT * DIM];
__device__ __half g_K [(size_t)MTOT * DIM];
__device__ __half g_V [(size_t)MTOT * DIM];
__device__ __half g_Vt[(size_t)BB * DIM * SEQ];
__device__ __half g_S [(size_t)BB * SEQ * SEQ];

__device__ __forceinline__ uint32_t smem_u32(const void* p) {
    uint32_t a;
    asm("{ .reg .u64 t; cvta.to.shared.u64 t, %1; cvt.u32.u64 %0, t; }"
        : "=r"(a) : "l"(p));
    return a;
}

#define CP_ASYNC16(dst, src) \
    asm volatile("cp.async.cg.shared.global [%0], [%1], 16;" :: "r"(dst), "l"(src) : "memory")
#define CP_COMMIT()  asm volatile("cp.async.commit_group;" ::: "memory")
#define CP_WAIT(n)   asm volatile("cp.async.wait_group %0;" :: "n"(n) : "memory")

__device__ __forceinline__ void mma_f16(float& c0, float& c1, float& c2, float& c3,
                                        uint32_t a0, uint32_t a1, uint32_t a2, uint32_t a3,
                                        uint32_t b0, uint32_t b1) {
    asm volatile(
        "mma.sync.aligned.m16n8k16.row.col.f32.f16.f16.f32 "
        "{%0,%1,%2,%3}, {%4,%5,%6,%7}, {%8,%9}, {%0,%1,%2,%3};"
        : "+f"(c0), "+f"(c1), "+f"(c2), "+f"(c3)
        : "r"(a0), "r"(a1), "r"(a2), "r"(a3), "r"(b0), "r"(b1));
}

// ---------------------------------------------------------------------------
// 128x128 x K tile GEMM core (NT: C[i][j] = scale * sum_k A[i][k]*B[j][k]).
// 128 threads = 4 warps (2x2), warp tile 64x64. BK=64 halves, double-buffered.
// Row stride 72 halves (144B): row starts at 16r mod 128 -> conflict-free.
// ---------------------------------------------------------------------------
#define BK 64
#define KST 72                     // halves
#define TILE_H (128 * KST)         // halves per operand per stage
#define SMEM_DYN (4 * TILE_H * 2)  // 2 ops * 2 stages * 18432B = 73728B

__device__ __forceinline__ void load_tile(uint32_t smBase,
                                          const __half* __restrict__ G,
                                          int ld, int k0, int t) {
#pragma unroll
    for (int i = 0; i < 8; i++) {
        int idx = t + i * 128;          // 0..1023
        int row = idx >> 3, seg = idx & 7;      // 8 x 16B per 128B row
        uint32_t d = smBase + (uint32_t)(row * KST + seg * 8) * 2u;
        CP_ASYNC16(d, G + (size_t)row * ld + k0 + seg * 8);
    }
}

__device__ __forceinline__ void gemm_core(const __half* __restrict__ A,
                                          const __half* __restrict__ B,
                                          void* __restrict__ Cout, int outHalf,
                                          int lda, int ldb, int ldc,
                                          int nChunks, float scale) {
    extern __shared__ __half dsm[];
    const uint32_t smA = smem_u32(dsm);
    const uint32_t smB = smA + 2u * TILE_H * 2u;

    const int t = threadIdx.x;
    const int wid = t >> 5, lane = t & 31;
    const int gid = lane >> 2, t4 = lane & 3;
    const int baseM = (wid >> 1) * 64;
    const int baseN = (wid & 1) * 64;

    float acc[4][8][4] = {};

    load_tile(smA, A, lda, 0, t);
    load_tile(smB, B, ldb, 0, t);
    CP_COMMIT();

    for (int c = 0; c < nChunks; c++) {
        const int s = c & 1;
        if (c + 1 < nChunks) {
            const uint32_t so = (uint32_t)((s ^ 1) * TILE_H) * 2u;
            load_tile(smA + so, A, lda, (c + 1) * BK, t);
            load_tile(smB + so, B, ldb, (c + 1) * BK, t);
            CP_COMMIT();
            CP_WAIT(1);
        } else {
            CP_WAIT(0);
        }
        __syncthreads();

        const uint32_t* As = (const uint32_t*)(dsm + (size_t)s * TILE_H);
        const uint32_t* Bs = (const uint32_t*)(dsm + 2 * TILE_H + (size_t)s * TILE_H);

#pragma unroll
        for (int kk = 0; kk < BK; kk += 16) {
            // 32-bit word index within a row: half index / 2
            const int kw = (kk >> 1) + t4;          // a0/b0 word
            uint32_t af[4][4], bf[8][2];
#pragma unroll
            for (int mt = 0; mt < 4; mt++) {
                const uint32_t* p0 = As + (size_t)(baseM + mt * 16 + gid) * (KST / 2) + kw;
                const uint32_t* p1 = As + (size_t)(baseM + mt * 16 + 8 + gid) * (KST / 2) + kw;
                af[mt][0] = p0[0];
                af[mt][1] = p1[0];
                af[mt][2] = p0[4];
                af[mt][3] = p1[4];
            }
#pragma unroll
            for (int nt = 0; nt < 8; nt++) {
                const uint32_t* q = Bs + (size_t)(baseN + nt * 8 + gid) * (KST / 2) + kw;
                bf[nt][0] = q[0];
                bf[nt][1] = q[4];
            }
#pragma unroll
            for (int mt = 0; mt < 4; mt++)
#pragma unroll
                for (int nt = 0; nt < 8; nt++)
                    mma_f16(acc[mt][nt][0], acc[mt][nt][1], acc[mt][nt][2], acc[mt][nt][3],
                            af[mt][0], af[mt][1], af[mt][2], af[mt][3],
                            bf[nt][0], bf[nt][1]);
        }
        __syncthreads();
    }

    // epilogue
#pragma unroll
    for (int mt = 0; mt < 4; mt++) {
        const int r0 = baseM + mt * 16 + gid;
#pragma unroll
        for (int nt = 0; nt < 8; nt++) {
            const int col = baseN + nt * 8 + t4 * 2;
            if (outHalf) {
                __half* Ch = (__half*)Cout;
                *(__half2*)(Ch + (size_t)r0 * ldc + col) =
                    __float22half2_rn(make_float2(acc[mt][nt][0] * scale, acc[mt][nt][1] * scale));
                *(__half2*)(Ch + (size_t)(r0 + 8) * ldc + col) =
                    __float22half2_rn(make_float2(acc[mt][nt][2] * scale, acc[mt][nt][3] * scale));
            } else {
                float* Cf = (float*)Cout;
                *(float2*)(Cf + (size_t)r0 * ldc + col) =
                    make_float2(acc[mt][nt][0] * scale, acc[mt][nt][1] * scale);
                *(float2*)(Cf + (size_t)(r0 + 8) * ldc + col) =
                    make_float2(acc[mt][nt][2] * scale, acc[mt][nt][3] * scale);
            }
        }
    }
}

// ---------------------------------------------------------------------------
// Prep / transpose kernels
// ---------------------------------------------------------------------------
__global__ void __launch_bounds__(256) prep_x(const float* __restrict__ x) {
    size_t i = (size_t)blockIdx.x * 256 + threadIdx.x;   // float4 index
    float4 v = ((const float4*)x)[i];
    __half2 h0 = __float22half2_rn(make_float2(v.x, v.y));
    __half2 h1 = __float22half2_rn(make_float2(v.z, v.w));
    ((__half2*)g_Xr)[i * 2] = h0;
    ((__half2*)g_Xr)[i * 2 + 1] = h1;
}

__global__ void __launch_bounds__(256) transpose_w(const float* __restrict__ Wq,
                                                   const float* __restrict__ Wk,
                                                   const float* __restrict__ Wv) {
    __shared__ float tile[32][33];
    const int z = blockIdx.z;
    const float* W = (z == 0) ? Wq : (z == 1) ? Wk : Wv;
    __half* Wt = g_Wt[z];
    const int nBase = blockIdx.x * 32, kBase = blockIdx.y * 32;
    const int tx = threadIdx.x & 31, ty = threadIdx.x >> 5;
#pragma unroll
    for (int r = 0; r < 32; r += 8)
        tile[ty + r][tx] = W[(size_t)(kBase + ty + r) * DIM + nBase + tx];
    __syncthreads();
#pragma unroll
    for (int r = 0; r < 32; r += 8)
        Wt[(size_t)(nBase + ty + r) * DIM + kBase + tx] = __float2half_rn(tile[tx][ty + r]);
}

__global__ void __launch_bounds__(256) transpose_v() {
    __shared__ __half tile[32][34];
    const int b = blockIdx.z;
    const int mBase = blockIdx.x * 32, dBase = blockIdx.y * 32;
    const __half* V = g_V + (size_t)b * SEQ * DIM;
    __half* Vt = g_Vt + (size_t)b * DIM * SEQ;
    const int tx = threadIdx.x & 31, ty = threadIdx.x >> 5;
#pragma unroll
    for (int r = 0; r < 32; r += 8)
        tile[ty + r][tx] = V[(size_t)(mBase + ty + r) * DIM + dBase + tx];
    __syncthreads();
#pragma unroll
    for (int r = 0; r < 32; r += 8)
        Vt[(size_t)(dBase + ty + r) * SEQ + mBase + tx] = tile[tx][ty + r];
}

// ---------------------------------------------------------------------------
// GEMM wrappers
// ---------------------------------------------------------------------------
__global__ void __launch_bounds__(128, 2) qkv_gemm() {
    const int nb = blockIdx.x, mb = blockIdx.y, z = blockIdx.z;
    const __half* A = g_Xr + (size_t)mb * 128 * DIM;
    const __half* B = g_Wt[z] + (size_t)nb * 128 * DIM;
    __half* outp = (z == 0) ? g_Q : (z == 1) ? g_K : g_V;
    __half* C = outp + (size_t)mb * 128 * DIM + nb * 128;
    gemm_core(A, B, C, 1, DIM, DIM, DIM, DIM / BK, 1.0f);
}

__global__ void __launch_bounds__(128, 2) scores_gemm() {
    const int jb = blockIdx.x, ib = blockIdx.y, b = blockIdx.z;
    if (jb > ib) return;                       // causal pruning
    const __half* A = g_Q + ((size_t)b * SEQ + ib * 128) * DIM;
    const __half* B = g_K + ((size_t)b * SEQ + jb * 128) * DIM;
    __half* C = g_S + (size_t)b * SEQ * SEQ + (size_t)ib * 128 * SEQ + jb * 128;
    gemm_core(A, B, C, 1, DIM, DIM, SEQ, DIM / BK, 0.03125f);
}

__global__ void __launch_bounds__(128, 2) pv_gemm(float* __restrict__ Out) {
    const int db = blockIdx.x, ib = blockIdx.y, b = blockIdx.z;
    const __half* A = g_S + (size_t)b * SEQ * SEQ + (size_t)ib * 128 * SEQ;
    const __half* B = g_Vt + ((size_t)b * DIM + db * 128) * SEQ;
    float* C = Out + ((size_t)b * SEQ + ib * 128) * DIM + db * 128;
    gemm_core(A, B, C, 0, SEQ, SEQ, DIM, (ib + 1) * 128 / BK, 1.0f);
}

// ---------------------------------------------------------------------------
// Causal softmax on half S; zero-pads row to diagonal 128-block boundary.
// ---------------------------------------------------------------------------
__global__ void __launch_bounds__(256) softmax_kernel() {
    const int row = blockIdx.x;
    const int b = row >> 11;
    const int i = row & (SEQ - 1);
    __half* Srow = g_S + (size_t)b * SEQ * SEQ + (size_t)i * SEQ;
    const int L = i + 1;
    const int Lpad = ((i >> 7) + 1) << 7;
    const int t = threadIdx.x;

    float vals[8];
    float mx = -CUDART_INF_F;
#pragma unroll
    for (int r = 0; r < 8; r++) {
        const int j = t + r * 256;
        vals[r] = (j < L) ? __half2float(Srow[j]) : -CUDART_INF_F;
        mx = fmaxf(mx, vals[r]);
    }
    __shared__ float red[256];
    red[t] = mx;
    __syncthreads();
    for (int s = 128; s > 0; s >>= 1) {
        if (t < s) red[t] = fmaxf(red[t], red[t + s]);
        __syncthreads();
    }
    mx = red[0];
    __syncthreads();

    float sum = 0.f;
#pragma unroll
    for (int r = 0; r < 8; r++) {
        const int j = t + r * 256;
        vals[r] = (j < L) ? __expf(vals[r] - mx) : 0.f;
        sum += vals[r];
    }
    red[t] = sum;
    __syncthreads();
    for (int s = 128; s > 0; s >>= 1) {
        if (t < s) red[t] += red[t + s];
        __syncthreads();
    }
    const float inv = 1.f / red[0];
#pragma unroll
    for (int r = 0; r < 8; r++) {
        const int j = t + r * 256;
        if (j < Lpad) Srow[j] = __float2half_rn(vals[r] * inv);
    }
}

// ---------------------------------------------------------------------------
extern "C" void kernel_launch(void* const* d_in, const int* in_sizes, int n_in,
                              void* d_out, int out_size) {
    const float* x  = (const float*)d_in[0];
    const float* Wq = (const float*)d_in[1];
    const float* Wk = (const float*)d_in[2];
    const float* Wv = (const float*)d_in[3];
    float* out = (float*)d_out;

    static int attrDone = 0;
    if (!attrDone) {
        cudaFuncSetAttribute(qkv_gemm,    cudaFuncAttributeMaxDynamicSharedMemorySize, SMEM_DYN);
        cudaFuncSetAttribute(scores_gemm, cudaFuncAttributeMaxDynamicSharedMemorySize, SMEM_DYN);
        cudaFuncSetAttribute(pv_gemm,     cudaFuncAttributeMaxDynamicSharedMemorySize, SMEM_DYN);
        attrDone = 1;
    }

    prep_x<<<(MTOT * DIM / 4) / 256, 256>>>(x);
    transpose_w<<<dim3(32, 32, 3), 256>>>(Wq, Wk, Wv);
    qkv_gemm<<<dim3(DIM / 128, MTOT / 128, 3), 128, SMEM_DYN>>>();
    transpose_v<<<dim3(SEQ / 32, DIM / 32, BB), 256>>>();
    scores_gemm<<<dim3(SEQ / 128, SEQ / 128, BB), 128, SMEM_DYN>>>();
    softmax_kernel<<<MTOT, 256>>>();
    pv_gemm<<<dim3(DIM / 128, SEQ / 128, BB), 128, SMEM_DYN>>>(out);
}

// round 7
// speedup vs baseline: 7.2486x; 1.6277x over previous
#include <cuda_runtime.h>
#include <cuda_fp16.h>
#include <math_constants.h>
#include <cstdint>

// ---------------------------------------------------------------------------
// CausalAttention B=8, N=2048, d=1024, fp32 I/O — fp16 mma.sync path.
// R7: ldmatrix.m8n8.x4 fragment loads (8 LDSM vs 32 LDS per warp k16-step).
// ---------------------------------------------------------------------------

#define BB   8
#define SEQ  2048
#define DIM  1024
#define MTOT (BB * SEQ)

__device__ __half g_Xr[(size_t)MTOT * DIM];
__device__ __half g_Wt[3][(size_t)DIM * DIM];
__device__ __half g_Q [(size_t)MTOT * DIM];
__device__ __half g_K [(size_t)MTOT * DIM];
__device__ __half g_V [(size_t)MTOT * DIM];
__device__ __half g_Vt[(size_t)BB * DIM * SEQ];
__device__ __half g_S [(size_t)BB * SEQ * SEQ];

__device__ __forceinline__ uint32_t smem_u32(const void* p) {
    uint32_t a;
    asm("{ .reg .u64 t; cvta.to.shared.u64 t, %1; cvt.u32.u64 %0, t; }"
        : "=r"(a) : "l"(p));
    return a;
}

#define CP_ASYNC16(dst, src) \
    asm volatile("cp.async.cg.shared.global [%0], [%1], 16;" :: "r"(dst), "l"(src) : "memory")
#define CP_COMMIT()  asm volatile("cp.async.commit_group;" ::: "memory")
#define CP_WAIT(n)   asm volatile("cp.async.wait_group %0;" :: "n"(n) : "memory")

#define LDSM4(r0, r1, r2, r3, addr) \
    asm volatile("ldmatrix.sync.aligned.m8n8.x4.shared.b16 {%0,%1,%2,%3}, [%4];" \
                 : "=r"(r0), "=r"(r1), "=r"(r2), "=r"(r3) : "r"(addr))

__device__ __forceinline__ void mma_f16(float& c0, float& c1, float& c2, float& c3,
                                        uint32_t a0, uint32_t a1, uint32_t a2, uint32_t a3,
                                        uint32_t b0, uint32_t b1) {
    asm volatile(
        "mma.sync.aligned.m16n8k16.row.col.f32.f16.f16.f32 "
        "{%0,%1,%2,%3}, {%4,%5,%6,%7}, {%8,%9}, {%0,%1,%2,%3};"
        : "+f"(c0), "+f"(c1), "+f"(c2), "+f"(c3)
        : "r"(a0), "r"(a1), "r"(a2), "r"(a3), "r"(b0), "r"(b1));
}

// ---------------------------------------------------------------------------
// 128x128 x K tile GEMM core (NT). 128 threads = 4 warps (2x2), warp 64x64.
// BK=64 halves, double-buffered cp.async, ldmatrix fragment loads.
// Row stride KST=72 halves (144B): ldmatrix 8-row groups hit 8 distinct
// 16B banks (144 mod 128 = 16) -> conflict-free.
// ---------------------------------------------------------------------------
#define BK 64
#define KST 72
#define TILE_H (128 * KST)
#define SMEM_DYN (4 * TILE_H * 2)   // 73728 B -> 2 CTAs/SM

__device__ __forceinline__ void load_tile(uint32_t smBase,
                                          const __half* __restrict__ G,
                                          int ld, int k0, int t) {
#pragma unroll
    for (int i = 0; i < 8; i++) {
        int idx = t + i * 128;
        int row = idx >> 3, seg = idx & 7;
        uint32_t d = smBase + (uint32_t)(row * KST + seg * 8) * 2u;
        CP_ASYNC16(d, G + (size_t)row * ld + k0 + seg * 8);
    }
}

__device__ __forceinline__ void gemm_core(const __half* __restrict__ A,
                                          const __half* __restrict__ B,
                                          void* __restrict__ Cout, int outHalf,
                                          int lda, int ldb, int ldc,
                                          int nChunks, float scale) {
    extern __shared__ __half dsm[];
    const uint32_t smA = smem_u32(dsm);
    const uint32_t smB = smA + 2u * TILE_H * 2u;

    const int t = threadIdx.x;
    const int wid = t >> 5, lane = t & 31;
    const int gid = lane >> 2, t4 = lane & 3;
    const int lr = lane & 7, lm = lane >> 3;      // ldmatrix row / matrix id
    const int baseM = (wid >> 1) * 64;
    const int baseN = (wid & 1) * 64;

    // ldmatrix per-lane byte offsets within a stage (kk = 0)
    uint32_t aOff[4], bOff[4];
#pragma unroll
    for (int mt = 0; mt < 4; mt++)
        aOff[mt] = (uint32_t)((baseM + mt * 16 + (lm & 1) * 8 + lr) * KST + (lm >> 1) * 8) * 2u;
#pragma unroll
    for (int p = 0; p < 4; p++)
        bOff[p] = (uint32_t)((baseN + p * 16 + (lm >> 1) * 8 + lr) * KST + (lm & 1) * 8) * 2u;

    float acc[4][8][4] = {};

    load_tile(smA, A, lda, 0, t);
    load_tile(smB, B, ldb, 0, t);
    CP_COMMIT();

    for (int c = 0; c < nChunks; c++) {
        const int s = c & 1;
        if (c + 1 < nChunks) {
            const uint32_t so = (uint32_t)((s ^ 1) * TILE_H) * 2u;
            load_tile(smA + so, A, lda, (c + 1) * BK, t);
            load_tile(smB + so, B, ldb, (c + 1) * BK, t);
            CP_COMMIT();
            CP_WAIT(1);
        } else {
            CP_WAIT(0);
        }
        __syncthreads();

        const uint32_t stA = smA + (uint32_t)s * TILE_H * 2u;
        const uint32_t stB = smB + (uint32_t)s * TILE_H * 2u;

#pragma unroll
        for (int ks = 0; ks < BK / 16; ks++) {
            const uint32_t ko = (uint32_t)ks * 32u;   // 16 halves
            uint32_t af[4][4], bf[8][2];
#pragma unroll
            for (int mt = 0; mt < 4; mt++)
                LDSM4(af[mt][0], af[mt][1], af[mt][2], af[mt][3], stA + aOff[mt] + ko);
#pragma unroll
            for (int p = 0; p < 4; p++)
                LDSM4(bf[2 * p][0], bf[2 * p][1], bf[2 * p + 1][0], bf[2 * p + 1][1],
                      stB + bOff[p] + ko);
#pragma unroll
            for (int mt = 0; mt < 4; mt++)
#pragma unroll
                for (int nt = 0; nt < 8; nt++)
                    mma_f16(acc[mt][nt][0], acc[mt][nt][1], acc[mt][nt][2], acc[mt][nt][3],
                            af[mt][0], af[mt][1], af[mt][2], af[mt][3],
                            bf[nt][0], bf[nt][1]);
        }
        __syncthreads();
    }

#pragma unroll
    for (int mt = 0; mt < 4; mt++) {
        const int r0 = baseM + mt * 16 + gid;
#pragma unroll
        for (int nt = 0; nt < 8; nt++) {
            const int col = baseN + nt * 8 + t4 * 2;
            if (outHalf) {
                __half* Ch = (__half*)Cout;
                *(__half2*)(Ch + (size_t)r0 * ldc + col) =
                    __float22half2_rn(make_float2(acc[mt][nt][0] * scale, acc[mt][nt][1] * scale));
                *(__half2*)(Ch + (size_t)(r0 + 8) * ldc + col) =
                    __float22half2_rn(make_float2(acc[mt][nt][2] * scale, acc[mt][nt][3] * scale));
            } else {
                float* Cf = (float*)Cout;
                *(float2*)(Cf + (size_t)r0 * ldc + col) =
                    make_float2(acc[mt][nt][0] * scale, acc[mt][nt][1] * scale);
                *(float2*)(Cf + (size_t)(r0 + 8) * ldc + col) =
                    make_float2(acc[mt][nt][2] * scale, acc[mt][nt][3] * scale);
            }
        }
    }
}

// ---------------------------------------------------------------------------
// Prep / transpose kernels
// ---------------------------------------------------------------------------
__global__ void __launch_bounds__(256) prep_x(const float* __restrict__ x) {
    size_t i = (size_t)blockIdx.x * 256 + threadIdx.x;
    float4 v = ((const float4*)x)[i];
    ((__half2*)g_Xr)[i * 2]     = __float22half2_rn(make_float2(v.x, v.y));
    ((__half2*)g_Xr)[i * 2 + 1] = __float22half2_rn(make_float2(v.z, v.w));
}

__global__ void __launch_bounds__(256) transpose_w(const float* __restrict__ Wq,
                                                   const float* __restrict__ Wk,
                                                   const float* __restrict__ Wv) {
    __shared__ float tile[32][33];
    const int z = blockIdx.z;
    const float* W = (z == 0) ? Wq : (z == 1) ? Wk : Wv;
    __half* Wt = g_Wt[z];
    const int nBase = blockIdx.x * 32, kBase = blockIdx.y * 32;
    const int tx = threadIdx.x & 31, ty = threadIdx.x >> 5;
#pragma unroll
    for (int r = 0; r < 32; r += 8)
        tile[ty + r][tx] = W[(size_t)(kBase + ty + r) * DIM + nBase + tx];
    __syncthreads();
#pragma unroll
    for (int r = 0; r < 32; r += 8)
        Wt[(size_t)(nBase + ty + r) * DIM + kBase + tx] = __float2half_rn(tile[tx][ty + r]);
}

__global__ void __launch_bounds__(256) transpose_v() {
    __shared__ __half tile[32][34];
    const int b = blockIdx.z;
    const int mBase = blockIdx.x * 32, dBase = blockIdx.y * 32;
    const __half* V = g_V + (size_t)b * SEQ * DIM;
    __half* Vt = g_Vt + (size_t)b * DIM * SEQ;
    const int tx = threadIdx.x & 31, ty = threadIdx.x >> 5;
#pragma unroll
    for (int r = 0; r < 32; r += 8)
        tile[ty + r][tx] = V[(size_t)(mBase + ty + r) * DIM + dBase + tx];
    __syncthreads();
#pragma unroll
    for (int r = 0; r < 32; r += 8)
        Vt[(size_t)(dBase + ty + r) * SEQ + mBase + tx] = tile[tx][ty + r];
}

// ---------------------------------------------------------------------------
// GEMM wrappers
// ---------------------------------------------------------------------------
__global__ void __launch_bounds__(128, 2) qkv_gemm() {
    const int nb = blockIdx.x, mb = blockIdx.y, z = blockIdx.z;
    const __half* A = g_Xr + (size_t)mb * 128 * DIM;
    const __half* B = g_Wt[z] + (size_t)nb * 128 * DIM;
    __half* outp = (z == 0) ? g_Q : (z == 1) ? g_K : g_V;
    __half* C = outp + (size_t)mb * 128 * DIM + nb * 128;
    gemm_core(A, B, C, 1, DIM, DIM, DIM, DIM / BK, 1.0f);
}

__global__ void __launch_bounds__(128, 2) scores_gemm() {
    const int jb = blockIdx.x, ib = blockIdx.y, b = blockIdx.z;
    if (jb > ib) return;
    const __half* A = g_Q + ((size_t)b * SEQ + ib * 128) * DIM;
    const __half* B = g_K + ((size_t)b * SEQ + jb * 128) * DIM;
    __half* C = g_S + (size_t)b * SEQ * SEQ + (size_t)ib * 128 * SEQ + jb * 128;
    gemm_core(A, B, C, 1, DIM, DIM, SEQ, DIM / BK, 0.03125f);
}

__global__ void __launch_bounds__(128, 2) pv_gemm(float* __restrict__ Out) {
    const int db = blockIdx.x, ib = blockIdx.y, b = blockIdx.z;
    const __half* A = g_S + (size_t)b * SEQ * SEQ + (size_t)ib * 128 * SEQ;
    const __half* B = g_Vt + ((size_t)b * DIM + db * 128) * SEQ;
    float* C = Out + ((size_t)b * SEQ + ib * 128) * DIM + db * 128;
    gemm_core(A, B, C, 0, SEQ, SEQ, DIM, (ib + 1) * 128 / BK, 1.0f);
}

// ---------------------------------------------------------------------------
// Causal softmax on half S; zero-pads row to diagonal 128-block boundary.
// ---------------------------------------------------------------------------
__global__ void __launch_bounds__(256) softmax_kernel() {
    const int row = blockIdx.x;
    const int b = row >> 11;
    const int i = row & (SEQ - 1);
    __half* Srow = g_S + (size_t)b * SEQ * SEQ + (size_t)i * SEQ;
    const int L = i + 1;
    const int Lpad = ((i >> 7) + 1) << 7;
    const int t = threadIdx.x;

    float vals[8];
    float mx = -CUDART_INF_F;
#pragma unroll
    for (int r = 0; r < 8; r++) {
        const int j = t + r * 256;
        vals[r] = (j < L) ? __half2float(Srow[j]) : -CUDART_INF_F;
        mx = fmaxf(mx, vals[r]);
    }
    __shared__ float red[256];
    red[t] = mx;
    __syncthreads();
    for (int s = 128; s > 0; s >>= 1) {
        if (t < s) red[t] = fmaxf(red[t], red[t + s]);
        __syncthreads();
    }
    mx = red[0];
    __syncthreads();

    float sum = 0.f;
#pragma unroll
    for (int r = 0; r < 8; r++) {
        const int j = t + r * 256;
        vals[r] = (j < L) ? __expf(vals[r] - mx) : 0.f;
        sum += vals[r];
    }
    red[t] = sum;
    __syncthreads();
    for (int s = 128; s > 0; s >>= 1) {
        if (t < s) red[t] += red[t + s];
        __syncthreads();
    }
    const float inv = 1.f / red[0];
#pragma unroll
    for (int r = 0; r < 8; r++) {
        const int j = t + r * 256;
        if (j < Lpad) Srow[j] = __float2half_rn(vals[r] * inv);
    }
}

// ---------------------------------------------------------------------------
extern "C" void kernel_launch(void* const* d_in, const int* in_sizes, int n_in,
                              void* d_out, int out_size) {
    const float* x  = (const float*)d_in[0];
    const float* Wq = (const float*)d_in[1];
    const float* Wk = (const float*)d_in[2];
    const float* Wv = (const float*)d_in[3];
    float* out = (float*)d_out;

    static int attrDone = 0;
    if (!attrDone) {
        cudaFuncSetAttribute(qkv_gemm,    cudaFuncAttributeMaxDynamicSharedMemorySize, SMEM_DYN);
        cudaFuncSetAttribute(scores_gemm, cudaFuncAttributeMaxDynamicSharedMemorySize, SMEM_DYN);
        cudaFuncSetAttribute(pv_gemm,     cudaFuncAttributeMaxDynamicSharedMemorySize, SMEM_DYN);
        attrDone = 1;
    }

    prep_x<<<(MTOT * DIM / 4) / 256, 256>>>(x);
    transpose_w<<<dim3(32, 32, 3), 256>>>(Wq, Wk, Wv);
    qkv_gemm<<<dim3(DIM / 128, MTOT / 128, 3), 128, SMEM_DYN>>>();
    transpose_v<<<dim3(SEQ / 32, DIM / 32, BB), 256>>>();
    scores_gemm<<<dim3(SEQ / 128, SEQ / 128, BB), 128, SMEM_DYN>>>();
    softmax_kernel<<<MTOT, 256>>>();
    pv_gemm<<<dim3(DIM / 128, SEQ / 128, BB), 128, SMEM_DYN>>>(out);
}

// round 9
// speedup vs baseline: 7.4501x; 1.0278x over previous
#include <cuda_runtime.h>
#include <cuda_fp16.h>
#include <math_constants.h>
#include <cstdint>

// ---------------------------------------------------------------------------
// CausalAttention B=8, N=2048, d=1024, fp32 I/O — fp16 mma.sync path.
// R8: pv uses ldmatrix.trans to read V directly (k-major) — transpose_v and
// g_Vt eliminated. qkv/scores cores unchanged from R7 (at legacy-HMMA ceiling).
// ---------------------------------------------------------------------------

#define BB   8
#define SEQ  2048
#define DIM  1024
#define MTOT (BB * SEQ)

__device__ __half g_Xr[(size_t)MTOT * DIM];
__device__ __half g_Wt[3][(size_t)DIM * DIM];
__device__ __half g_Q [(size_t)MTOT * DIM];
__device__ __half g_K [(size_t)MTOT * DIM];
__device__ __half g_V [(size_t)MTOT * DIM];
__device__ __half g_S [(size_t)BB * SEQ * SEQ];

__device__ __forceinline__ uint32_t smem_u32(const void* p) {
    uint32_t a;
    asm("{ .reg .u64 t; cvta.to.shared.u64 t, %1; cvt.u32.u64 %0, t; }"
        : "=r"(a) : "l"(p));
    return a;
}

#define CP_ASYNC16(dst, src) \
    asm volatile("cp.async.cg.shared.global [%0], [%1], 16;" :: "r"(dst), "l"(src) : "memory")
#define CP_COMMIT()  asm volatile("cp.async.commit_group;" ::: "memory")
#define CP_WAIT(n)   asm volatile("cp.async.wait_group %0;" :: "n"(n) : "memory")

#define LDSM4(r0, r1, r2, r3, addr) \
    asm volatile("ldmatrix.sync.aligned.m8n8.x4.shared.b16 {%0,%1,%2,%3}, [%4];" \
                 : "=r"(r0), "=r"(r1), "=r"(r2), "=r"(r3) : "r"(addr))
#define LDSM4T(r0, r1, r2, r3, addr) \
    asm volatile("ldmatrix.sync.aligned.m8n8.x4.trans.shared.b16 {%0,%1,%2,%3}, [%4];" \
                 : "=r"(r0), "=r"(r1), "=r"(r2), "=r"(r3) : "r"(addr))

__device__ __forceinline__ void mma_f16(float& c0, float& c1, float& c2, float& c3,
                                        uint32_t a0, uint32_t a1, uint32_t a2, uint32_t a3,
                                        uint32_t b0, uint32_t b1) {
    asm volatile(
        "mma.sync.aligned.m16n8k16.row.col.f32.f16.f16.f32 "
        "{%0,%1,%2,%3}, {%4,%5,%6,%7}, {%8,%9}, {%0,%1,%2,%3};"
        : "+f"(c0), "+f"(c1), "+f"(c2), "+f"(c3)
        : "r"(a0), "r"(a1), "r"(a2), "r"(a3), "r"(b0), "r"(b1));
}

// ---------------------------------------------------------------------------
// NT core (unchanged from R7): A,B both K-major. 4 warps, warp 64x64, BK=64.
// ---------------------------------------------------------------------------
#define BK 64
#define KST 72
#define TILE_H (128 * KST)
#define SMEM_DYN (4 * TILE_H * 2)   // 73728 B -> 2 CTAs/SM

__device__ __forceinline__ void load_tile(uint32_t smBase,
                                          const __half* __restrict__ G,
                                          int ld, int k0, int t) {
#pragma unroll
    for (int i = 0; i < 8; i++) {
        int idx = t + i * 128;
        int row = idx >> 3, seg = idx & 7;
        uint32_t d = smBase + (uint32_t)(row * KST + seg * 8) * 2u;
        CP_ASYNC16(d, G + (size_t)row * ld + k0 + seg * 8);
    }
}

__device__ __forceinline__ void gemm_core(const __half* __restrict__ A,
                                          const __half* __restrict__ B,
                                          void* __restrict__ Cout, int outHalf,
                                          int lda, int ldb, int ldc,
                                          int nChunks, float scale) {
    extern __shared__ __half dsm[];
    const uint32_t smA = smem_u32(dsm);
    const uint32_t smB = smA + 2u * TILE_H * 2u;

    const int t = threadIdx.x;
    const int wid = t >> 5, lane = t & 31;
    const int gid = lane >> 2, t4 = lane & 3;
    const int lr = lane & 7, lm = lane >> 3;
    const int baseM = (wid >> 1) * 64;
    const int baseN = (wid & 1) * 64;

    uint32_t aOff[4], bOff[4];
#pragma unroll
    for (int mt = 0; mt < 4; mt++)
        aOff[mt] = (uint32_t)((baseM + mt * 16 + (lm & 1) * 8 + lr) * KST + (lm >> 1) * 8) * 2u;
#pragma unroll
    for (int p = 0; p < 4; p++)
        bOff[p] = (uint32_t)((baseN + p * 16 + (lm >> 1) * 8 + lr) * KST + (lm & 1) * 8) * 2u;

    float acc[4][8][4] = {};

    load_tile(smA, A, lda, 0, t);
    load_tile(smB, B, ldb, 0, t);
    CP_COMMIT();

    for (int c = 0; c < nChunks; c++) {
        const int s = c & 1;
        if (c + 1 < nChunks) {
            const uint32_t so = (uint32_t)((s ^ 1) * TILE_H) * 2u;
            load_tile(smA + so, A, lda, (c + 1) * BK, t);
            load_tile(smB + so, B, ldb, (c + 1) * BK, t);
            CP_COMMIT();
            CP_WAIT(1);
        } else {
            CP_WAIT(0);
        }
        __syncthreads();

        const uint32_t stA = smA + (uint32_t)s * TILE_H * 2u;
        const uint32_t stB = smB + (uint32_t)s * TILE_H * 2u;

#pragma unroll
        for (int ks = 0; ks < BK / 16; ks++) {
            const uint32_t ko = (uint32_t)ks * 32u;
            uint32_t af[4][4], bf[8][2];
#pragma unroll
            for (int mt = 0; mt < 4; mt++)
                LDSM4(af[mt][0], af[mt][1], af[mt][2], af[mt][3], stA + aOff[mt] + ko);
#pragma unroll
            for (int p = 0; p < 4; p++)
                LDSM4(bf[2 * p][0], bf[2 * p][1], bf[2 * p + 1][0], bf[2 * p + 1][1],
                      stB + bOff[p] + ko);
#pragma unroll
            for (int mt = 0; mt < 4; mt++)
#pragma unroll
                for (int nt = 0; nt < 8; nt++)
                    mma_f16(acc[mt][nt][0], acc[mt][nt][1], acc[mt][nt][2], acc[mt][nt][3],
                            af[mt][0], af[mt][1], af[mt][2], af[mt][3],
                            bf[nt][0], bf[nt][1]);
        }
        __syncthreads();
    }

#pragma unroll
    for (int mt = 0; mt < 4; mt++) {
        const int r0 = baseM + mt * 16 + gid;
#pragma unroll
        for (int nt = 0; nt < 8; nt++) {
            const int col = baseN + nt * 8 + t4 * 2;
            if (outHalf) {
                __half* Ch = (__half*)Cout;
                *(__half2*)(Ch + (size_t)r0 * ldc + col) =
                    __float22half2_rn(make_float2(acc[mt][nt][0] * scale, acc[mt][nt][1] * scale));
                *(__half2*)(Ch + (size_t)(r0 + 8) * ldc + col) =
                    __float22half2_rn(make_float2(acc[mt][nt][2] * scale, acc[mt][nt][3] * scale));
            } else {
                float* Cf = (float*)Cout;
                *(float2*)(Cf + (size_t)r0 * ldc + col) =
                    make_float2(acc[mt][nt][0] * scale, acc[mt][nt][1] * scale);
                *(float2*)(Cf + (size_t)(r0 + 8) * ldc + col) =
                    make_float2(acc[mt][nt][2] * scale, acc[mt][nt][3] * scale);
            }
        }
    }
}

// ---------------------------------------------------------------------------
// NN core for PV: A = P (k-major), B = V (row-major [k][n]) read with
// ldmatrix.trans — no pre-transposed V needed.
// B tile: BK=64 k-rows x 128 n-cols, stride 136 halves (272B; 272 mod 128 =
// 16 -> 8-row ldmatrix groups and cp.async rows conflict-free).
// ---------------------------------------------------------------------------
#define KSTB 136
#define BTILE_H (64 * KSTB)                    // halves per B stage
#define SMEM_PV (2 * TILE_H * 2 + 2 * BTILE_H * 2)   // 36864 + 34816 = 71680

__device__ __forceinline__ void load_tile_v(uint32_t smBase,
                                            const __half* __restrict__ G,
                                            int ld, int k0, int nBase, int t) {
#pragma unroll
    for (int i = 0; i < 8; i++) {
        int idx = t + i * 128;                 // 0..1023
        int row = idx >> 4, seg = idx & 15;    // 64 rows x 16 x 16B
        uint32_t d = smBase + (uint32_t)(row * KSTB + seg * 8) * 2u;
        CP_ASYNC16(d, G + (size_t)(k0 + row) * ld + nBase + seg * 8);
    }
}

__device__ __forceinline__ void gemm_core_nn(const __half* __restrict__ A,
                                             const __half* __restrict__ B,
                                             float* __restrict__ Cout,
                                             int lda, int ldb, int ldc, int nBase0,
                                             int nChunks, float scale) {
    extern __shared__ __half dsm[];
    const uint32_t smA = smem_u32(dsm);
    const uint32_t smB = smA + 2u * TILE_H * 2u;

    const int t = threadIdx.x;
    const int wid = t >> 5, lane = t & 31;
    const int gid = lane >> 2, t4 = lane & 3;
    const int lr = lane & 7, lm = lane >> 3;
    const int baseM = (wid >> 1) * 64;
    const int baseN = (wid & 1) * 64;

    uint32_t aOff[4], bOff[4];
#pragma unroll
    for (int mt = 0; mt < 4; mt++)
        aOff[mt] = (uint32_t)((baseM + mt * 16 + (lm & 1) * 8 + lr) * KST + (lm >> 1) * 8) * 2u;
    // trans-B: row = (lm&1)*8 + lr (k), col = (lm>>1)*8 (n) within 16x16 block
#pragma unroll
    for (int p = 0; p < 4; p++)
        bOff[p] = (uint32_t)(((lm & 1) * 8 + lr) * KSTB + baseN + p * 16 + (lm >> 1) * 8) * 2u;

    float acc[4][8][4] = {};

    load_tile(smA, A, lda, 0, t);
    load_tile_v(smB, B, ldb, 0, nBase0, t);
    CP_COMMIT();

    for (int c = 0; c < nChunks; c++) {
        const int s = c & 1;
        if (c + 1 < nChunks) {
            load_tile(smA + (uint32_t)((s ^ 1) * TILE_H) * 2u, A, lda, (c + 1) * BK, t);
            load_tile_v(smB + (uint32_t)((s ^ 1) * BTILE_H) * 2u, B, ldb, (c + 1) * BK, nBase0, t);
            CP_COMMIT();
            CP_WAIT(1);
        } else {
            CP_WAIT(0);
        }
        __syncthreads();

        const uint32_t stA = smA + (uint32_t)s * TILE_H * 2u;
        const uint32_t stB = smB + (uint32_t)s * BTILE_H * 2u;

#pragma unroll
        for (int ks = 0; ks < BK / 16; ks++) {
            const uint32_t koA = (uint32_t)ks * 32u;            // 16 halves along k
            const uint32_t koB = (uint32_t)ks * 16u * KSTB * 2u; // 16 k-rows
            uint32_t af[4][4], bf[8][2];
#pragma unroll
            for (int mt = 0; mt < 4; mt++)
                LDSM4(af[mt][0], af[mt][1], af[mt][2], af[mt][3], stA + aOff[mt] + koA);
#pragma unroll
            for (int p = 0; p < 4; p++)
                LDSM4T(bf[2 * p][0], bf[2 * p][1], bf[2 * p + 1][0], bf[2 * p + 1][1],
                       stB + bOff[p] + koB);
#pragma unroll
            for (int mt = 0; mt < 4; mt++)
#pragma unroll
                for (int nt = 0; nt < 8; nt++)
                    mma_f16(acc[mt][nt][0], acc[mt][nt][1], acc[mt][nt][2], acc[mt][nt][3],
                            af[mt][0], af[mt][1], af[mt][2], af[mt][3],
                            bf[nt][0], bf[nt][1]);
        }
        __syncthreads();
    }

#pragma unroll
    for (int mt = 0; mt < 4; mt++) {
        const int r0 = baseM + mt * 16 + gid;
#pragma unroll
        for (int nt = 0; nt < 8; nt++) {
            const int col = baseN + nt * 8 + t4 * 2;
            *(float2*)(Cout + (size_t)r0 * ldc + col) =
                make_float2(acc[mt][nt][0] * scale, acc[mt][nt][1] * scale);
            *(float2*)(Cout + (size_t)(r0 + 8) * ldc + col) =
                make_float2(acc[mt][nt][2] * scale, acc[mt][nt][3] * scale);
        }
    }
}

// ---------------------------------------------------------------------------
// Prep / transpose kernels
// ---------------------------------------------------------------------------
__global__ void __launch_bounds__(256) prep_x(const float* __restrict__ x) {
    size_t i = (size_t)blockIdx.x * 256 + threadIdx.x;
    float4 v = ((const float4*)x)[i];
    ((__half2*)g_Xr)[i * 2]     = __float22half2_rn(make_float2(v.x, v.y));
    ((__half2*)g_Xr)[i * 2 + 1] = __float22half2_rn(make_float2(v.z, v.w));
}

__global__ void __launch_bounds__(256) transpose_w(const float* __restrict__ Wq,
                                                   const float* __restrict__ Wk,
                                                   const float* __restrict__ Wv) {
    __shared__ float tile[32][33];
    const int z = blockIdx.z;
    const float* W = (z == 0) ? Wq : (z == 1) ? Wk : Wv;
    __half* Wt = g_Wt[z];
    const int nBase = blockIdx.x * 32, kBase = blockIdx.y * 32;
    const int tx = threadIdx.x & 31, ty = threadIdx.x >> 5;
#pragma unroll
    for (int r = 0; r < 32; r += 8)
        tile[ty + r][tx] = W[(size_t)(kBase + ty + r) * DIM + nBase + tx];
    __syncthreads();
#pragma unroll
    for (int r = 0; r < 32; r += 8)
        Wt[(size_t)(nBase + ty + r) * DIM + kBase + tx] = __float2half_rn(tile[tx][ty + r]);
}

// ---------------------------------------------------------------------------
// GEMM wrappers
// ---------------------------------------------------------------------------
__global__ void __launch_bounds__(128, 2) qkv_gemm() {
    const int nb = blockIdx.x, mb = blockIdx.y, z = blockIdx.z;
    const __half* A = g_Xr + (size_t)mb * 128 * DIM;
    const __half* B = g_Wt[z] + (size_t)nb * 128 * DIM;
    __half* outp = (z == 0) ? g_Q : (z == 1) ? g_K : g_V;
    __half* C = outp + (size_t)mb * 128 * DIM + nb * 128;
    gemm_core(A, B, C, 1, DIM, DIM, DIM, DIM / BK, 1.0f);
}

__global__ void __launch_bounds__(128, 2) scores_gemm() {
    const int jb = blockIdx.x, ib = blockIdx.y, b = blockIdx.z;
    if (jb > ib) return;
    const __half* A = g_Q + ((size_t)b * SEQ + ib * 128) * DIM;
    const __half* B = g_K + ((size_t)b * SEQ + jb * 128) * DIM;
    __half* C = g_S + (size_t)b * SEQ * SEQ + (size_t)ib * 128 * SEQ + jb * 128;
    gemm_core(A, B, C, 1, DIM, DIM, SEQ, DIM / BK, 0.03125f);
}

__global__ void __launch_bounds__(128, 2) pv_gemm(float* __restrict__ Out) {
    const int db = blockIdx.x, ib = blockIdx.y, b = blockIdx.z;
    const __half* A = g_S + (size_t)b * SEQ * SEQ + (size_t)ib * 128 * SEQ;
    const __half* B = g_V + (size_t)b * SEQ * DIM;     // k-major, read via trans
    float* C = Out + ((size_t)b * SEQ + ib * 128) * DIM + db * 128;
    gemm_core_nn(A, B, C, SEQ, DIM, DIM, db * 128, (ib + 1) * 128 / BK, 1.0f);
}

// ---------------------------------------------------------------------------
// Causal softmax on half S; zero-pads row to diagonal 128-block boundary.
// ---------------------------------------------------------------------------
__global__ void __launch_bounds__(256) softmax_kernel() {
    const int row = blockIdx.x;
    const int b = row >> 11;
    const int i = row & (SEQ - 1);
    __half* Srow = g_S + (size_t)b * SEQ * SEQ + (size_t)i * SEQ;
    const int L = i + 1;
    const int Lpad = ((i >> 7) + 1) << 7;
    const int t = threadIdx.x;

    float vals[8];
    float mx = -CUDART_INF_F;
#pragma unroll
    for (int r = 0; r < 8; r++) {
        const int j = t + r * 256;
        vals[r] = (j < L) ? __half2float(Srow[j]) : -CUDART_INF_F;
        mx = fmaxf(mx, vals[r]);
    }
    __shared__ float red[256];
    red[t] = mx;
    __syncthreads();
    for (int s = 128; s > 0; s >>= 1) {
        if (t < s) red[t] = fmaxf(red[t], red[t + s]);
        __syncthreads();
    }
    mx = red[0];
    __syncthreads();

    float sum = 0.f;
#pragma unroll
    for (int r = 0; r < 8; r++) {
        const int j = t + r * 256;
        vals[r] = (j < L) ? __expf(vals[r] - mx) : 0.f;
        sum += vals[r];
    }
    red[t] = sum;
    __syncthreads();
    for (int s = 128; s > 0; s >>= 1) {
        if (t < s) red[t] += red[t + s];
        __syncthreads();
    }
    const float inv = 1.f / red[0];
#pragma unroll
    for (int r = 0; r < 8; r++) {
        const int j = t + r * 256;
        if (j < Lpad) Srow[j] = __float2half_rn(vals[r] * inv);
    }
}

// ---------------------------------------------------------------------------
extern "C" void kernel_launch(void* const* d_in, const int* in_sizes, int n_in,
                              void* d_out, int out_size) {
    const float* x  = (const float*)d_in[0];
    const float* Wq = (const float*)d_in[1];
    const float* Wk = (const float*)d_in[2];
    const float* Wv = (const float*)d_in[3];
    float* out = (float*)d_out;

    static int attrDone = 0;
    if (!attrDone) {
        cudaFuncSetAttribute(qkv_gemm,    cudaFuncAttributeMaxDynamicSharedMemorySize, SMEM_DYN);
        cudaFuncSetAttribute(scores_gemm, cudaFuncAttributeMaxDynamicSharedMemorySize, SMEM_DYN);
        cudaFuncSetAttribute(pv_gemm,     cudaFuncAttributeMaxDynamicSharedMemorySize, SMEM_PV);
        attrDone = 1;
    }

    prep_x<<<(MTOT * DIM / 4) / 256, 256>>>(x);
    transpose_w<<<dim3(32, 32, 3), 256>>>(Wq, Wk, Wv);
    qkv_gemm<<<dim3(DIM / 128, MTOT / 128, 3), 128, SMEM_DYN>>>();
    scores_gemm<<<dim3(SEQ / 128, SEQ / 128, BB), 128, SMEM_DYN>>>();
    softmax_kernel<<<MTOT, 256>>>();
    pv_gemm<<<dim3(DIM / 128, SEQ / 128, BB), 128, SMEM_PV>>>(out);
}

// round 10
// speedup vs baseline: 7.5248x; 1.0100x over previous
#include <cuda_runtime.h>
#include <cuda_fp16.h>
#include <math_constants.h>
#include <cstdint>

// ---------------------------------------------------------------------------
// CausalAttention B=8, N=2048, d=1024, fp32 I/O — fp16 mma.sync path.
// R10: 256-thread GEMM CTAs (8 warps, warp tile 64x32) -> 16 warps/SM to
// feed the tensor pipe (was 50.8% busy at 8 warps/SM).
// ---------------------------------------------------------------------------

#define BB   8
#define SEQ  2048
#define DIM  1024
#define MTOT (BB * SEQ)

__device__ __half g_Xr[(size_t)MTOT * DIM];
__device__ __half g_Wt[3][(size_t)DIM * DIM];
__device__ __half g_Q [(size_t)MTOT * DIM];
__device__ __half g_K [(size_t)MTOT * DIM];
__device__ __half g_V [(size_t)MTOT * DIM];
__device__ __half g_S [(size_t)BB * SEQ * SEQ];

__device__ __forceinline__ uint32_t smem_u32(const void* p) {
    uint32_t a;
    asm("{ .reg .u64 t; cvta.to.shared.u64 t, %1; cvt.u32.u64 %0, t; }"
        : "=r"(a) : "l"(p));
    return a;
}

#define CP_ASYNC16(dst, src) \
    asm volatile("cp.async.cg.shared.global [%0], [%1], 16;" :: "r"(dst), "l"(src) : "memory")
#define CP_COMMIT()  asm volatile("cp.async.commit_group;" ::: "memory")
#define CP_WAIT(n)   asm volatile("cp.async.wait_group %0;" :: "n"(n) : "memory")

#define LDSM4(r0, r1, r2, r3, addr) \
    asm volatile("ldmatrix.sync.aligned.m8n8.x4.shared.b16 {%0,%1,%2,%3}, [%4];" \
                 : "=r"(r0), "=r"(r1), "=r"(r2), "=r"(r3) : "r"(addr))
#define LDSM4T(r0, r1, r2, r3, addr) \
    asm volatile("ldmatrix.sync.aligned.m8n8.x4.trans.shared.b16 {%0,%1,%2,%3}, [%4];" \
                 : "=r"(r0), "=r"(r1), "=r"(r2), "=r"(r3) : "r"(addr))

__device__ __forceinline__ void mma_f16(float& c0, float& c1, float& c2, float& c3,
                                        uint32_t a0, uint32_t a1, uint32_t a2, uint32_t a3,
                                        uint32_t b0, uint32_t b1) {
    asm volatile(
        "mma.sync.aligned.m16n8k16.row.col.f32.f16.f16.f32 "
        "{%0,%1,%2,%3}, {%4,%5,%6,%7}, {%8,%9}, {%0,%1,%2,%3};"
        : "+f"(c0), "+f"(c1), "+f"(c2), "+f"(c3)
        : "r"(a0), "r"(a1), "r"(a2), "r"(a3), "r"(b0), "r"(b1));
}

// ---------------------------------------------------------------------------
// NT core: A,B both K-major. 256 threads = 8 warps (2x4), warp tile 64x32.
// BK=64, KST=72 halves; double-buffered cp.async; ldmatrix fragments.
// ---------------------------------------------------------------------------
#define BK 64
#define KST 72
#define TILE_H (128 * KST)
#define SMEM_DYN (4 * TILE_H * 2)   // 73728 B -> 2 CTAs/SM

__device__ __forceinline__ void load_tile(uint32_t smBase,
                                          const __half* __restrict__ G,
                                          int ld, int k0, int t) {
#pragma unroll
    for (int i = 0; i < 4; i++) {
        int idx = t + i * 256;
        int row = idx >> 3, seg = idx & 7;
        uint32_t d = smBase + (uint32_t)(row * KST + seg * 8) * 2u;
        CP_ASYNC16(d, G + (size_t)row * ld + k0 + seg * 8);
    }
}

__device__ __forceinline__ void gemm_core(const __half* __restrict__ A,
                                          const __half* __restrict__ B,
                                          void* __restrict__ Cout, int outHalf,
                                          int lda, int ldb, int ldc,
                                          int nChunks, float scale) {
    extern __shared__ __half dsm[];
    const uint32_t smA = smem_u32(dsm);
    const uint32_t smB = smA + 2u * TILE_H * 2u;

    const int t = threadIdx.x;
    const int wid = t >> 5, lane = t & 31;
    const int gid = lane >> 2, t4 = lane & 3;
    const int lr = lane & 7, lm = lane >> 3;
    const int baseM = (wid >> 2) * 64;     // warpM 0..1
    const int baseN = (wid & 3) * 32;      // warpN 0..3

    uint32_t aOff[4], bOff[2];
#pragma unroll
    for (int mt = 0; mt < 4; mt++)
        aOff[mt] = (uint32_t)((baseM + mt * 16 + (lm & 1) * 8 + lr) * KST + (lm >> 1) * 8) * 2u;
#pragma unroll
    for (int p = 0; p < 2; p++)
        bOff[p] = (uint32_t)((baseN + p * 16 + (lm >> 1) * 8 + lr) * KST + (lm & 1) * 8) * 2u;

    float acc[4][4][4] = {};

    load_tile(smA, A, lda, 0, t);
    load_tile(smB, B, ldb, 0, t);
    CP_COMMIT();

    for (int c = 0; c < nChunks; c++) {
        const int s = c & 1;
        if (c + 1 < nChunks) {
            const uint32_t so = (uint32_t)((s ^ 1) * TILE_H) * 2u;
            load_tile(smA + so, A, lda, (c + 1) * BK, t);
            load_tile(smB + so, B, ldb, (c + 1) * BK, t);
            CP_COMMIT();
            CP_WAIT(1);
        } else {
            CP_WAIT(0);
        }
        __syncthreads();

        const uint32_t stA = smA + (uint32_t)s * TILE_H * 2u;
        const uint32_t stB = smB + (uint32_t)s * TILE_H * 2u;

#pragma unroll
        for (int ks = 0; ks < BK / 16; ks++) {
            const uint32_t ko = (uint32_t)ks * 32u;
            uint32_t af[4][4], bf[4][2];
#pragma unroll
            for (int mt = 0; mt < 4; mt++)
                LDSM4(af[mt][0], af[mt][1], af[mt][2], af[mt][3], stA + aOff[mt] + ko);
#pragma unroll
            for (int p = 0; p < 2; p++)
                LDSM4(bf[2 * p][0], bf[2 * p][1], bf[2 * p + 1][0], bf[2 * p + 1][1],
                      stB + bOff[p] + ko);
#pragma unroll
            for (int mt = 0; mt < 4; mt++)
#pragma unroll
                for (int nt = 0; nt < 4; nt++)
                    mma_f16(acc[mt][nt][0], acc[mt][nt][1], acc[mt][nt][2], acc[mt][nt][3],
                            af[mt][0], af[mt][1], af[mt][2], af[mt][3],
                            bf[nt][0], bf[nt][1]);
        }
        __syncthreads();
    }

#pragma unroll
    for (int mt = 0; mt < 4; mt++) {
        const int r0 = baseM + mt * 16 + gid;
#pragma unroll
        for (int nt = 0; nt < 4; nt++) {
            const int col = baseN + nt * 8 + t4 * 2;
            if (outHalf) {
                __half* Ch = (__half*)Cout;
                *(__half2*)(Ch + (size_t)r0 * ldc + col) =
                    __float22half2_rn(make_float2(acc[mt][nt][0] * scale, acc[mt][nt][1] * scale));
                *(__half2*)(Ch + (size_t)(r0 + 8) * ldc + col) =
                    __float22half2_rn(make_float2(acc[mt][nt][2] * scale, acc[mt][nt][3] * scale));
            } else {
                float* Cf = (float*)Cout;
                *(float2*)(Cf + (size_t)r0 * ldc + col) =
                    make_float2(acc[mt][nt][0] * scale, acc[mt][nt][1] * scale);
                *(float2*)(Cf + (size_t)(r0 + 8) * ldc + col) =
                    make_float2(acc[mt][nt][2] * scale, acc[mt][nt][3] * scale);
            }
        }
    }
}

// ---------------------------------------------------------------------------
// NN core for PV: A = P (k-major), B = V (row-major [k][n]) via ldmatrix.trans.
// ---------------------------------------------------------------------------
#define KSTB 136
#define BTILE_H (64 * KSTB)
#define SMEM_PV (2 * TILE_H * 2 + 2 * BTILE_H * 2)   // 71680 B

__device__ __forceinline__ void load_tile_v(uint32_t smBase,
                                            const __half* __restrict__ G,
                                            int ld, int k0, int nBase, int t) {
#pragma unroll
    for (int i = 0; i < 4; i++) {
        int idx = t + i * 256;
        int row = idx >> 4, seg = idx & 15;
        uint32_t d = smBase + (uint32_t)(row * KSTB + seg * 8) * 2u;
        CP_ASYNC16(d, G + (size_t)(k0 + row) * ld + nBase + seg * 8);
    }
}

__device__ __forceinline__ void gemm_core_nn(const __half* __restrict__ A,
                                             const __half* __restrict__ B,
                                             float* __restrict__ Cout,
                                             int lda, int ldb, int ldc, int nBase0,
                                             int nChunks, float scale) {
    extern __shared__ __half dsm[];
    const uint32_t smA = smem_u32(dsm);
    const uint32_t smB = smA + 2u * TILE_H * 2u;

    const int t = threadIdx.x;
    const int wid = t >> 5, lane = t & 31;
    const int gid = lane >> 2, t4 = lane & 3;
    const int lr = lane & 7, lm = lane >> 3;
    const int baseM = (wid >> 2) * 64;
    const int baseN = (wid & 3) * 32;

    uint32_t aOff[4], bOff[2];
#pragma unroll
    for (int mt = 0; mt < 4; mt++)
        aOff[mt] = (uint32_t)((baseM + mt * 16 + (lm & 1) * 8 + lr) * KST + (lm >> 1) * 8) * 2u;
#pragma unroll
    for (int p = 0; p < 2; p++)
        bOff[p] = (uint32_t)(((lm & 1) * 8 + lr) * KSTB + baseN + p * 16 + (lm >> 1) * 8) * 2u;

    float acc[4][4][4] = {};

    load_tile(smA, A, lda, 0, t);
    load_tile_v(smB, B, ldb, 0, nBase0, t);
    CP_COMMIT();

    for (int c = 0; c < nChunks; c++) {
        const int s = c & 1;
        if (c + 1 < nChunks) {
            load_tile(smA + (uint32_t)((s ^ 1) * TILE_H) * 2u, A, lda, (c + 1) * BK, t);
            load_tile_v(smB + (uint32_t)((s ^ 1) * BTILE_H) * 2u, B, ldb, (c + 1) * BK, nBase0, t);
            CP_COMMIT();
            CP_WAIT(1);
        } else {
            CP_WAIT(0);
        }
        __syncthreads();

        const uint32_t stA = smA + (uint32_t)s * TILE_H * 2u;
        const uint32_t stB = smB + (uint32_t)s * BTILE_H * 2u;

#pragma unroll
        for (int ks = 0; ks < BK / 16; ks++) {
            const uint32_t koA = (uint32_t)ks * 32u;
            const uint32_t koB = (uint32_t)ks * 16u * KSTB * 2u;
            uint32_t af[4][4], bf[4][2];
#pragma unroll
            for (int mt = 0; mt < 4; mt++)
                LDSM4(af[mt][0], af[mt][1], af[mt][2], af[mt][3], stA + aOff[mt] + koA);
#pragma unroll
            for (int p = 0; p < 2; p++)
                LDSM4T(bf[2 * p][0], bf[2 * p][1], bf[2 * p + 1][0], bf[2 * p + 1][1],
                       stB + bOff[p] + koB);
#pragma unroll
            for (int mt = 0; mt < 4; mt++)
#pragma unroll
                for (int nt = 0; nt < 4; nt++)
                    mma_f16(acc[mt][nt][0], acc[mt][nt][1], acc[mt][nt][2], acc[mt][nt][3],
                            af[mt][0], af[mt][1], af[mt][2], af[mt][3],
                            bf[nt][0], bf[nt][1]);
        }
        __syncthreads();
    }

#pragma unroll
    for (int mt = 0; mt < 4; mt++) {
        const int r0 = baseM + mt * 16 + gid;
#pragma unroll
        for (int nt = 0; nt < 4; nt++) {
            const int col = baseN + nt * 8 + t4 * 2;
            *(float2*)(Cout + (size_t)r0 * ldc + col) =
                make_float2(acc[mt][nt][0] * scale, acc[mt][nt][1] * scale);
            *(float2*)(Cout + (size_t)(r0 + 8) * ldc + col) =
                make_float2(acc[mt][nt][2] * scale, acc[mt][nt][3] * scale);
        }
    }
}

// ---------------------------------------------------------------------------
// Prep / transpose kernels
// ---------------------------------------------------------------------------
__global__ void __launch_bounds__(256) prep_x(const float* __restrict__ x) {
    size_t i = (size_t)blockIdx.x * 256 + threadIdx.x;
    float4 v = ((const float4*)x)[i];
    ((__half2*)g_Xr)[i * 2]     = __float22half2_rn(make_float2(v.x, v.y));
    ((__half2*)g_Xr)[i * 2 + 1] = __float22half2_rn(make_float2(v.z, v.w));
}

__global__ void __launch_bounds__(256) transpose_w(const float* __restrict__ Wq,
                                                   const float* __restrict__ Wk,
                                                   const float* __restrict__ Wv) {
    __shared__ float tile[32][33];
    const int z = blockIdx.z;
    const float* W = (z == 0) ? Wq : (z == 1) ? Wk : Wv;
    __half* Wt = g_Wt[z];
    const int nBase = blockIdx.x * 32, kBase = blockIdx.y * 32;
    const int tx = threadIdx.x & 31, ty = threadIdx.x >> 5;
#pragma unroll
    for (int r = 0; r < 32; r += 8)
        tile[ty + r][tx] = W[(size_t)(kBase + ty + r) * DIM + nBase + tx];
    __syncthreads();
#pragma unroll
    for (int r = 0; r < 32; r += 8)
        Wt[(size_t)(nBase + ty + r) * DIM + kBase + tx] = __float2half_rn(tile[tx][ty + r]);
}

// ---------------------------------------------------------------------------
// GEMM wrappers (256 threads, 2 CTAs/SM)
// ---------------------------------------------------------------------------
__global__ void __launch_bounds__(256, 2) qkv_gemm() {
    const int nb = blockIdx.x, mb = blockIdx.y, z = blockIdx.z;
    const __half* A = g_Xr + (size_t)mb * 128 * DIM;
    const __half* B = g_Wt[z] + (size_t)nb * 128 * DIM;
    __half* outp = (z == 0) ? g_Q : (z == 1) ? g_K : g_V;
    __half* C = outp + (size_t)mb * 128 * DIM + nb * 128;
    gemm_core(A, B, C, 1, DIM, DIM, DIM, DIM / BK, 1.0f);
}

__global__ void __launch_bounds__(256, 2) scores_gemm() {
    const int jb = blockIdx.x, ib = blockIdx.y, b = blockIdx.z;
    if (jb > ib) return;
    const __half* A = g_Q + ((size_t)b * SEQ + ib * 128) * DIM;
    const __half* B = g_K + ((size_t)b * SEQ + jb * 128) * DIM;
    __half* C = g_S + (size_t)b * SEQ * SEQ + (size_t)ib * 128 * SEQ + jb * 128;
    gemm_core(A, B, C, 1, DIM, DIM, SEQ, DIM / BK, 0.03125f);
}

__global__ void __launch_bounds__(256, 2) pv_gemm(float* __restrict__ Out) {
    const int db = blockIdx.x, ib = blockIdx.y, b = blockIdx.z;
    const __half* A = g_S + (size_t)b * SEQ * SEQ + (size_t)ib * 128 * SEQ;
    const __half* B = g_V + (size_t)b * SEQ * DIM;
    float* C = Out + ((size_t)b * SEQ + ib * 128) * DIM + db * 128;
    gemm_core_nn(A, B, C, SEQ, DIM, DIM, db * 128, (ib + 1) * 128 / BK, 1.0f);
}

// ---------------------------------------------------------------------------
// Causal softmax on half S; zero-pads row to diagonal 128-block boundary.
// ---------------------------------------------------------------------------
__global__ void __launch_bounds__(256) softmax_kernel() {
    const int row = blockIdx.x;
    const int b = row >> 11;
    const int i = row & (SEQ - 1);
    __half* Srow = g_S + (size_t)b * SEQ * SEQ + (size_t)i * SEQ;
    const int L = i + 1;
    const int Lpad = ((i >> 7) + 1) << 7;
    const int t = threadIdx.x;

    float vals[8];
    float mx = -CUDART_INF_F;
#pragma unroll
    for (int r = 0; r < 8; r++) {
        const int j = t + r * 256;
        vals[r] = (j < L) ? __half2float(Srow[j]) : -CUDART_INF_F;
        mx = fmaxf(mx, vals[r]);
    }
    __shared__ float red[256];
    red[t] = mx;
    __syncthreads();
    for (int s = 128; s > 0; s >>= 1) {
        if (t < s) red[t] = fmaxf(red[t], red[t + s]);
        __syncthreads();
    }
    mx = red[0];
    __syncthreads();

    float sum = 0.f;
#pragma unroll
    for (int r = 0; r < 8; r++) {
        const int j = t + r * 256;
        vals[r] = (j < L) ? __expf(vals[r] - mx) : 0.f;
        sum += vals[r];
    }
    red[t] = sum;
    __syncthreads();
    for (int s = 128; s > 0; s >>= 1) {
        if (t < s) red[t] += red[t + s];
        __syncthreads();
    }
    const float inv = 1.f / red[0];
#pragma unroll
    for (int r = 0; r < 8; r++) {
        const int j = t + r * 256;
        if (j < Lpad) Srow[j] = __float2half_rn(vals[r] * inv);
    }
}

// ---------------------------------------------------------------------------
extern "C" void kernel_launch(void* const* d_in, const int* in_sizes, int n_in,
                              void* d_out, int out_size) {
    const float* x  = (const float*)d_in[0];
    const float* Wq = (const float*)d_in[1];
    const float* Wk = (const float*)d_in[2];
    const float* Wv = (const float*)d_in[3];
    float* out = (float*)d_out;

    static int attrDone = 0;
    if (!attrDone) {
        cudaFuncSetAttribute(qkv_gemm,    cudaFuncAttributeMaxDynamicSharedMemorySize, SMEM_DYN);
        cudaFuncSetAttribute(scores_gemm, cudaFuncAttributeMaxDynamicSharedMemorySize, SMEM_DYN);
        cudaFuncSetAttribute(pv_gemm,     cudaFuncAttributeMaxDynamicSharedMemorySize, SMEM_PV);
        attrDone = 1;
    }

    prep_x<<<(MTOT * DIM / 4) / 256, 256>>>(x);
    transpose_w<<<dim3(32, 32, 3), 256>>>(Wq, Wk, Wv);
    qkv_gemm<<<dim3(DIM / 128, MTOT / 128, 3), 256, SMEM_DYN>>>();
    scores_gemm<<<dim3(SEQ / 128, SEQ / 128, BB), 256, SMEM_DYN>>>();
    softmax_kernel<<<MTOT, 256>>>();
    pv_gemm<<<dim3(DIM / 128, SEQ / 128, BB), 256, SMEM_PV>>>(out);
}